// round 5
// baseline (speedup 1.0000x reference)
#include <cuda_runtime.h>

// GraphNet NodeModel, algebraically factored:
//   edge_msg = relu( Xa[dst] + Xb[src] + Ea + Ue[batch[dst]] ),  Ea = edge_attr @ W1c.T
//   agg      = segment_sum(edge_msg, dst)        (fp32 atomics)
//   out      = relu( Xc + agg @ W2b.T + Un[batch] )
// where Xa/Xb/Xc are per-node GEMMs and Ue/Un per-graph GEMMs, all fp32.

#define FD 128
#define MAXN 50000
#define MAXE 800000
#define MAXG 64

__device__ float g_Xa[MAXN * FD];    // x @ W1[:,0:128].T      (dest part)
__device__ float g_Xb[MAXN * FD];    // x @ W1[:,128:256].T    (source part)
__device__ float g_Xc[MAXN * FD];    // x @ W2[:,0:128].T + b2
__device__ float g_agg[MAXN * FD];   // segment-summed edge messages
__device__ float g_Ue[MAXG * FD];    // u @ W1[:,384:512].T + b1
__device__ float g_Un[MAXG * FD];    // u @ W2[:,256:384].T
__device__ int   g_is64;             // 1 if indices are int64, 0 if int32

__device__ __forceinline__ long long ld_idx(const void* p, long long i, int is64) {
    if (is64) return ((const long long*)p)[i];
    return (long long)((const int*)p)[i];
}

// ---------------------------------------------------------------------------
// Detect index dtype: for int64 little-endian values < 2^31, every odd 32-bit
// word is zero. Sample the first 64 pairs of edge_index's src section.
// ---------------------------------------------------------------------------
__global__ void sniff_kernel(const unsigned int* __restrict__ ei) {
    int is64 = 1;
#pragma unroll 1
    for (int k = 1; k < 129; k += 2) {
        if (ei[k] != 0u) { is64 = 0; break; }
    }
    g_is64 = is64;
}

__global__ void zero_kernel(int n4) {
    int i = blockIdx.x * blockDim.x + threadIdx.x;
    if (i < n4)
        reinterpret_cast<float4*>(g_agg)[i] = make_float4(0.f, 0.f, 0.f, 0.f);
}

// ---------------------------------------------------------------------------
// Per-graph GEMMs (tiny: 64 x 128 each). Block = one graph, 128 threads.
// ---------------------------------------------------------------------------
__global__ void graph_kernel(const float* __restrict__ u,
                             const float* __restrict__ W1,
                             const float* __restrict__ b1,
                             const float* __restrict__ W2) {
    __shared__ float su[FD];
    int g = blockIdx.x;
    int o = threadIdx.x;
    su[o] = u[g * FD + o];
    __syncthreads();
    float a1 = b1[o];
    float a2 = 0.f;
    const float* w1r = W1 + o * 512 + 384;
    const float* w2r = W2 + o * 384 + 256;
#pragma unroll 8
    for (int k = 0; k < FD; k++) {
        a1 = fmaf(su[k], w1r[k], a1);
        a2 = fmaf(su[k], w2r[k], a2);
    }
    g_Ue[g * FD + o] = a1;
    g_Un[g * FD + o] = a2;
}

// ---------------------------------------------------------------------------
// Core tile GEMM: 128 rows x 128 cols x K=128, fp32 FFMA.
// 256 threads, 8x8 micro-tile per thread. A rows contiguous (stride 128),
// B = W[o*ldw + off + k] (W row-major [128, ldw]).
// ---------------------------------------------------------------------------
__device__ __forceinline__ void tile_gemm(
    const float* __restrict__ A, int rowBase, int M,
    const float* __restrict__ W, int ldw, int off,
    float (&acc)[8][8], float (*As)[132], float (*Bs)[132])
{
    const int tid = threadIdx.x;
    const int le = tid & 127;          // row (A) / out-col (W) being loaded
    const int lq = (tid >> 7) << 3;    // k sub-offset within 16-chunk (0 or 8)
    const int tx = tid & 15;           // micro-tile column group
    const int ty = tid >> 4;           // micro-tile row group

#pragma unroll 1
    for (int k0 = 0; k0 < 128; k0 += 16) {
        float4 v0, v1;
        int row = rowBase + le;
        if (row < M) {
            const float4* p = reinterpret_cast<const float4*>(
                A + (size_t)row * 128 + k0 + lq);
            v0 = p[0]; v1 = p[1];
        } else {
            v0 = make_float4(0.f, 0.f, 0.f, 0.f); v1 = v0;
        }
        const float4* q = reinterpret_cast<const float4*>(
            W + (size_t)le * ldw + off + k0 + lq);
        float4 w0 = q[0], w1 = q[1];

        __syncthreads();   // protect previous iteration's smem reads
        As[lq + 0][le] = v0.x; As[lq + 1][le] = v0.y;
        As[lq + 2][le] = v0.z; As[lq + 3][le] = v0.w;
        As[lq + 4][le] = v1.x; As[lq + 5][le] = v1.y;
        As[lq + 6][le] = v1.z; As[lq + 7][le] = v1.w;
        Bs[lq + 0][le] = w0.x; Bs[lq + 1][le] = w0.y;
        Bs[lq + 2][le] = w0.z; Bs[lq + 3][le] = w0.w;
        Bs[lq + 4][le] = w1.x; Bs[lq + 5][le] = w1.y;
        Bs[lq + 6][le] = w1.z; Bs[lq + 7][le] = w1.w;
        __syncthreads();

#pragma unroll
        for (int kk = 0; kk < 16; kk++) {
            float4 a0 = *reinterpret_cast<const float4*>(&As[kk][ty * 8]);
            float4 a1 = *reinterpret_cast<const float4*>(&As[kk][ty * 8 + 4]);
            float4 b0 = *reinterpret_cast<const float4*>(&Bs[kk][tx * 8]);
            float4 b1 = *reinterpret_cast<const float4*>(&Bs[kk][tx * 8 + 4]);
            float av[8] = {a0.x, a0.y, a0.z, a0.w, a1.x, a1.y, a1.z, a1.w};
            float bv[8] = {b0.x, b0.y, b0.z, b0.w, b1.x, b1.y, b1.z, b1.w};
#pragma unroll
            for (int i = 0; i < 8; i++)
#pragma unroll
                for (int j = 0; j < 8; j++)
                    acc[i][j] = fmaf(av[i], bv[j], acc[i][j]);
        }
    }
    __syncthreads();
}

// ---------------------------------------------------------------------------
// Precompute Xa / Xb / Xc: grid.y selects which product.
// ---------------------------------------------------------------------------
__global__ __launch_bounds__(256) void precompute_kernel(
    const float* __restrict__ x, const float* __restrict__ W1,
    const float* __restrict__ W2, const float* __restrict__ b2, int N)
{
    __shared__ float As[16][132];
    __shared__ float Bs[16][132];

    const float* W; int ldw, off; const float* bias; float* C;
    int which = blockIdx.y;
    if (which == 0)      { W = W1; ldw = 512; off = 0;   bias = 0;   C = g_Xa; }
    else if (which == 1) { W = W1; ldw = 512; off = 128; bias = 0;   C = g_Xb; }
    else                 { W = W2; ldw = 384; off = 0;   bias = b2;  C = g_Xc; }

    float acc[8][8];
#pragma unroll
    for (int i = 0; i < 8; i++)
#pragma unroll
        for (int j = 0; j < 8; j++) acc[i][j] = 0.f;

    int m0 = blockIdx.x * 128;
    tile_gemm(x, m0, N, W, ldw, off, acc, As, Bs);

    int tx = threadIdx.x & 15, ty = threadIdx.x >> 4;
    int c = tx * 8;
    float bb[8] = {0.f, 0.f, 0.f, 0.f, 0.f, 0.f, 0.f, 0.f};
    if (bias) {
        const float4* pb = reinterpret_cast<const float4*>(bias + c);
        float4 q0 = pb[0], q1 = pb[1];
        bb[0] = q0.x; bb[1] = q0.y; bb[2] = q0.z; bb[3] = q0.w;
        bb[4] = q1.x; bb[5] = q1.y; bb[6] = q1.z; bb[7] = q1.w;
    }
#pragma unroll
    for (int i = 0; i < 8; i++) {
        int row = m0 + ty * 8 + i;
        if (row < N) {
            float4 o0 = make_float4(acc[i][0] + bb[0], acc[i][1] + bb[1],
                                    acc[i][2] + bb[2], acc[i][3] + bb[3]);
            float4 o1 = make_float4(acc[i][4] + bb[4], acc[i][5] + bb[5],
                                    acc[i][6] + bb[6], acc[i][7] + bb[7]);
            float4* po = reinterpret_cast<float4*>(&C[(size_t)row * 128 + c]);
            po[0] = o0; po[1] = o1;
        }
    }
}

// ---------------------------------------------------------------------------
// Edge kernel: Ea = edge_attr @ W1c.T, fused gather epilogue + relu + atomic
// scatter-add into g_agg. 128 edges per block.
// ---------------------------------------------------------------------------
__global__ __launch_bounds__(256) void edge_kernel(
    const float* __restrict__ edge_attr, const float* __restrict__ W1,
    const void* __restrict__ ei, const void* __restrict__ batch, int E)
{
    __shared__ float As[16][132];
    __shared__ float Bs[16][132];
    __shared__ int sDst[128], sSrc[128], sGb[128];

    int e0 = blockIdx.x * 128;
    int tid = threadIdx.x;
    if (tid < 128) {
        int ge = e0 + tid;
        int is64 = g_is64;
        if (ge < E) {
            long long s = ld_idx(ei, ge, is64);
            long long d = ld_idx(ei, (long long)E + ge, is64);
            sSrc[tid] = (int)s;
            sDst[tid] = (int)d;
            sGb[tid] = (int)ld_idx(batch, d, is64);
        } else {
            sSrc[tid] = 0; sDst[tid] = 0; sGb[tid] = 0;
        }
    }

    float acc[8][8];
#pragma unroll
    for (int i = 0; i < 8; i++)
#pragma unroll
        for (int j = 0; j < 8; j++) acc[i][j] = 0.f;

    tile_gemm(edge_attr, e0, E, W1, 512, 256, acc, As, Bs);

    int tx = tid & 15, ty = tid >> 4;
    int c = tx * 8;
#pragma unroll
    for (int i = 0; i < 8; i++) {
        int e = ty * 8 + i;
        if (e0 + e < E) {
            int d = sDst[e], s = sSrc[e], g = sGb[e];
            const float4* pa = reinterpret_cast<const float4*>(&g_Xa[(size_t)d * 128 + c]);
            const float4* pb = reinterpret_cast<const float4*>(&g_Xb[(size_t)s * 128 + c]);
            const float4* pu = reinterpret_cast<const float4*>(&g_Ue[g * 128 + c]);
            float4 a0 = pa[0], a1 = pa[1];
            float4 b0 = pb[0], b1 = pb[1];
            float4 u0 = pu[0], u1 = pu[1];
            float va[8];
            va[0] = acc[i][0] + a0.x + b0.x + u0.x;
            va[1] = acc[i][1] + a0.y + b0.y + u0.y;
            va[2] = acc[i][2] + a0.z + b0.z + u0.z;
            va[3] = acc[i][3] + a0.w + b0.w + u0.w;
            va[4] = acc[i][4] + a1.x + b1.x + u1.x;
            va[5] = acc[i][5] + a1.y + b1.y + u1.y;
            va[6] = acc[i][6] + a1.z + b1.z + u1.z;
            va[7] = acc[i][7] + a1.w + b1.w + u1.w;
            float* dp = &g_agg[(size_t)d * 128 + c];
#pragma unroll
            for (int j = 0; j < 8; j++)
                atomicAdd(dp + j, fmaxf(va[j], 0.f));
        }
    }
}

// ---------------------------------------------------------------------------
// Node kernel: out = relu( Xc + agg @ W2[:,128:256].T + Un[batch] )
// ---------------------------------------------------------------------------
__global__ __launch_bounds__(256) void node_kernel(
    const float* __restrict__ W2, const void* __restrict__ batch,
    float* __restrict__ out, int N)
{
    __shared__ float As[16][132];
    __shared__ float Bs[16][132];

    int n0 = blockIdx.x * 128;
    float acc[8][8];
#pragma unroll
    for (int i = 0; i < 8; i++)
#pragma unroll
        for (int j = 0; j < 8; j++) acc[i][j] = 0.f;

    tile_gemm(g_agg, n0, N, W2, 384, 128, acc, As, Bs);

    int tid = threadIdx.x;
    int tx = tid & 15, ty = tid >> 4;
    int c = tx * 8;
    int is64 = g_is64;
#pragma unroll
    for (int i = 0; i < 8; i++) {
        int row = n0 + ty * 8 + i;
        if (row < N) {
            int g = (int)ld_idx(batch, row, is64);
            const float4* pc = reinterpret_cast<const float4*>(&g_Xc[(size_t)row * 128 + c]);
            const float4* pu = reinterpret_cast<const float4*>(&g_Un[g * 128 + c]);
            float4 c0 = pc[0], c1 = pc[1];
            float4 u0 = pu[0], u1 = pu[1];
            float4 o0, o1;
            o0.x = fmaxf(acc[i][0] + c0.x + u0.x, 0.f);
            o0.y = fmaxf(acc[i][1] + c0.y + u0.y, 0.f);
            o0.z = fmaxf(acc[i][2] + c0.z + u0.z, 0.f);
            o0.w = fmaxf(acc[i][3] + c0.w + u0.w, 0.f);
            o1.x = fmaxf(acc[i][4] + c1.x + u1.x, 0.f);
            o1.y = fmaxf(acc[i][5] + c1.y + u1.y, 0.f);
            o1.z = fmaxf(acc[i][6] + c1.z + u1.z, 0.f);
            o1.w = fmaxf(acc[i][7] + c1.w + u1.w, 0.f);
            float4* po = reinterpret_cast<float4*>(&out[(size_t)row * 128 + c]);
            po[0] = o0; po[1] = o1;
        }
    }
}

// ---------------------------------------------------------------------------
// Launch. Inputs (metadata order): x, edge_index, edge_attr, u, batch,
//                                  W1, b1, W2, b2. Output: float [N,128].
// ---------------------------------------------------------------------------
extern "C" void kernel_launch(void* const* d_in, const int* in_sizes, int n_in,
                              void* d_out, int out_size) {
    const float* x         = (const float*)d_in[0];
    const void*  ei        = d_in[1];
    const float* edge_attr = (const float*)d_in[2];
    const float* u         = (const float*)d_in[3];
    const void*  batch     = d_in[4];
    const float* W1        = (const float*)d_in[5];
    const float* b1        = (const float*)d_in[6];
    const float* W2        = (const float*)d_in[7];
    const float* b2        = (const float*)d_in[8];
    float* out = (float*)d_out;

    int N = in_sizes[0] / FD;
    int E = in_sizes[2] / FD;
    int G = in_sizes[3] / FD;

    sniff_kernel<<<1, 1>>>((const unsigned int*)ei);

    int n4 = N * (FD / 4);
    zero_kernel<<<(n4 + 255) / 256, 256>>>(n4);

    graph_kernel<<<G, FD>>>(u, W1, b1, W2);

    dim3 pg((N + 127) / 128, 3);
    precompute_kernel<<<pg, 256>>>(x, W1, W2, b2, N);

    edge_kernel<<<(E + 127) / 128, 256>>>(edge_attr, W1, ei, batch, E);

    node_kernel<<<(N + 127) / 128, 256>>>(W2, batch, out, N);
}

// round 6
// speedup vs baseline: 1.2081x; 1.2081x over previous
#include <cuda_runtime.h>

// GraphNet NodeModel, algebraically factored:
//   edge_msg = relu( Xa[dst] + Xb[src] + Ea + Ue[batch[dst]] ),  Ea = edge_attr @ W1c.T
//   agg      = segment_sum(edge_msg, dst)        (red.global.add.v4.f32)
//   out      = relu( Xc + agg @ W2b.T + Un[batch] )
// All GEMMs fp32 with packed fma.rn.f32x2 (2x FFMA issue rate on Blackwell).

#define FD 128
#define MAXN 50000
#define MAXE 800000
#define MAXG 64

__device__ float g_Xa[MAXN * FD];    // x @ W1[:,0:128].T      (dest part)
__device__ float g_Xb[MAXN * FD];    // x @ W1[:,128:256].T    (source part)
__device__ float g_Xc[MAXN * FD];    // x @ W2[:,0:128].T + b2
__device__ float g_agg[MAXN * FD];   // segment-summed edge messages
__device__ float g_Ue[MAXG * FD];    // u @ W1[:,384:512].T + b1
__device__ float g_Un[MAXG * FD];    // u @ W2[:,256:384].T
__device__ int   g_is64;             // 1 if indices are int64, 0 if int32

// ---------------- packed-f32x2 helpers ----------------
__device__ __forceinline__ unsigned long long pack2(float x) {
    unsigned long long r;
    asm("mov.b64 %0, {%1, %1};" : "=l"(r) : "r"(__float_as_uint(x)));
    return r;
}
__device__ __forceinline__ void ffma2(unsigned long long& d,
                                      unsigned long long a,
                                      unsigned long long b) {
    asm("fma.rn.f32x2 %0, %1, %2, %0;" : "+l"(d) : "l"(a), "l"(b));
}
__device__ __forceinline__ float2 unpk(unsigned long long v) {
    float2 f;
    asm("mov.b64 {%0, %1}, %2;" : "=f"(f.x), "=f"(f.y) : "l"(v));
    return f;
}
__device__ __forceinline__ void red_add_v4(float* p, float a, float b,
                                           float c, float d) {
    unsigned long long gp = (unsigned long long)__cvta_generic_to_global(p);
    asm volatile("red.global.add.v4.f32 [%0], {%1, %2, %3, %4};"
                 :: "l"(gp), "f"(a), "f"(b), "f"(c), "f"(d) : "memory");
}

__device__ __forceinline__ long long ld_idx(const void* p, long long i, int is64) {
    if (is64) return ((const long long*)p)[i];
    return (long long)((const int*)p)[i];
}

// ---------------------------------------------------------------------------
// Detect index dtype: for int64 little-endian values < 2^31, every odd 32-bit
// word is zero. Sample the first 64 pairs of edge_index's src section.
// ---------------------------------------------------------------------------
__global__ void sniff_kernel(const unsigned int* __restrict__ ei) {
    int is64 = 1;
#pragma unroll 1
    for (int k = 1; k < 129; k += 2) {
        if (ei[k] != 0u) { is64 = 0; break; }
    }
    g_is64 = is64;
}

__global__ void zero_kernel(int n4) {
    int i = blockIdx.x * blockDim.x + threadIdx.x;
    if (i < n4)
        reinterpret_cast<float4*>(g_agg)[i] = make_float4(0.f, 0.f, 0.f, 0.f);
}

// ---------------------------------------------------------------------------
// Per-graph GEMMs (tiny: 64 x 128 each). Block = one graph, 128 threads.
// ---------------------------------------------------------------------------
__global__ void graph_kernel(const float* __restrict__ u,
                             const float* __restrict__ W1,
                             const float* __restrict__ b1,
                             const float* __restrict__ W2) {
    __shared__ float su[FD];
    int g = blockIdx.x;
    int o = threadIdx.x;
    su[o] = u[g * FD + o];
    __syncthreads();
    float a1 = b1[o];
    float a2 = 0.f;
    const float* w1r = W1 + o * 512 + 384;
    const float* w2r = W2 + o * 384 + 256;
#pragma unroll 8
    for (int k = 0; k < FD; k++) {
        a1 = fmaf(su[k], w1r[k], a1);
        a2 = fmaf(su[k], w2r[k], a2);
    }
    g_Ue[g * FD + o] = a1;
    g_Un[g * FD + o] = a2;
}

// ---------------------------------------------------------------------------
// Core tile GEMM: 128 rows x 128 cols x K=128, packed f32x2 FMA.
// 256 threads, 8x8 micro-tile per thread (stored as 8x4 f32x2 pairs).
// A rows contiguous (stride 128), B = W[o*ldw + off + k] (row-major [128,ldw]).
// ---------------------------------------------------------------------------
__device__ __forceinline__ void tile_gemm(
    const float* __restrict__ A, int rowBase, int M,
    const float* __restrict__ W, int ldw, int off,
    unsigned long long (&acc)[8][4], float (*As)[132], float (*Bs)[132])
{
    const int tid = threadIdx.x;
    const int le = tid & 127;          // row (A) / out-col (W) being loaded
    const int lq = (tid >> 7) << 3;    // k sub-offset within 16-chunk (0 or 8)
    const int tx = tid & 15;           // micro-tile column group
    const int ty = tid >> 4;           // micro-tile row group

#pragma unroll 1
    for (int k0 = 0; k0 < 128; k0 += 16) {
        float4 v0, v1;
        int row = rowBase + le;
        if (row < M) {
            const float4* p = reinterpret_cast<const float4*>(
                A + (size_t)row * 128 + k0 + lq);
            v0 = p[0]; v1 = p[1];
        } else {
            v0 = make_float4(0.f, 0.f, 0.f, 0.f); v1 = v0;
        }
        const float4* q = reinterpret_cast<const float4*>(
            W + (size_t)le * ldw + off + k0 + lq);
        float4 w0 = q[0], w1 = q[1];

        __syncthreads();   // protect previous iteration's smem reads
        As[lq + 0][le] = v0.x; As[lq + 1][le] = v0.y;
        As[lq + 2][le] = v0.z; As[lq + 3][le] = v0.w;
        As[lq + 4][le] = v1.x; As[lq + 5][le] = v1.y;
        As[lq + 6][le] = v1.z; As[lq + 7][le] = v1.w;
        Bs[lq + 0][le] = w0.x; Bs[lq + 1][le] = w0.y;
        Bs[lq + 2][le] = w0.z; Bs[lq + 3][le] = w0.w;
        Bs[lq + 4][le] = w1.x; Bs[lq + 5][le] = w1.y;
        Bs[lq + 6][le] = w1.z; Bs[lq + 7][le] = w1.w;
        __syncthreads();

#pragma unroll
        for (int kk = 0; kk < 16; kk++) {
            float4 a0 = *reinterpret_cast<const float4*>(&As[kk][ty * 8]);
            float4 a1 = *reinterpret_cast<const float4*>(&As[kk][ty * 8 + 4]);
            ulonglong2 b01 = *reinterpret_cast<const ulonglong2*>(&Bs[kk][tx * 8]);
            ulonglong2 b23 = *reinterpret_cast<const ulonglong2*>(&Bs[kk][tx * 8 + 4]);
            unsigned long long av[8];
            av[0] = pack2(a0.x); av[1] = pack2(a0.y);
            av[2] = pack2(a0.z); av[3] = pack2(a0.w);
            av[4] = pack2(a1.x); av[5] = pack2(a1.y);
            av[6] = pack2(a1.z); av[7] = pack2(a1.w);
            unsigned long long bv[4] = {b01.x, b01.y, b23.x, b23.y};
#pragma unroll
            for (int i = 0; i < 8; i++)
#pragma unroll
                for (int j = 0; j < 4; j++)
                    ffma2(acc[i][j], av[i], bv[j]);
        }
    }
    __syncthreads();
}

__device__ __forceinline__ void zero_acc(unsigned long long (&acc)[8][4]) {
#pragma unroll
    for (int i = 0; i < 8; i++)
#pragma unroll
        for (int j = 0; j < 4; j++) acc[i][j] = 0ull;
}

// ---------------------------------------------------------------------------
// Precompute Xa / Xb / Xc: grid.y selects which product.
// ---------------------------------------------------------------------------
__global__ __launch_bounds__(256) void precompute_kernel(
    const float* __restrict__ x, const float* __restrict__ W1,
    const float* __restrict__ W2, const float* __restrict__ b2, int N)
{
    __shared__ __align__(16) float As[16][132];
    __shared__ __align__(16) float Bs[16][132];

    const float* W; int ldw, off; const float* bias; float* C;
    int which = blockIdx.y;
    if (which == 0)      { W = W1; ldw = 512; off = 0;   bias = 0;   C = g_Xa; }
    else if (which == 1) { W = W1; ldw = 512; off = 128; bias = 0;   C = g_Xb; }
    else                 { W = W2; ldw = 384; off = 0;   bias = b2;  C = g_Xc; }

    unsigned long long acc[8][4];
    zero_acc(acc);

    int m0 = blockIdx.x * 128;
    tile_gemm(x, m0, N, W, ldw, off, acc, As, Bs);

    int tx = threadIdx.x & 15, ty = threadIdx.x >> 4;
    int c = tx * 8;
    float bb[8] = {0.f, 0.f, 0.f, 0.f, 0.f, 0.f, 0.f, 0.f};
    if (bias) {
        const float4* pb = reinterpret_cast<const float4*>(bias + c);
        float4 q0 = pb[0], q1 = pb[1];
        bb[0] = q0.x; bb[1] = q0.y; bb[2] = q0.z; bb[3] = q0.w;
        bb[4] = q1.x; bb[5] = q1.y; bb[6] = q1.z; bb[7] = q1.w;
    }
#pragma unroll
    for (int i = 0; i < 8; i++) {
        int row = m0 + ty * 8 + i;
        if (row < N) {
            float2 p0 = unpk(acc[i][0]), p1 = unpk(acc[i][1]);
            float2 p2 = unpk(acc[i][2]), p3 = unpk(acc[i][3]);
            float4 o0 = make_float4(p0.x + bb[0], p0.y + bb[1],
                                    p1.x + bb[2], p1.y + bb[3]);
            float4 o1 = make_float4(p2.x + bb[4], p2.y + bb[5],
                                    p3.x + bb[6], p3.y + bb[7]);
            float4* po = reinterpret_cast<float4*>(&C[(size_t)row * 128 + c]);
            po[0] = o0; po[1] = o1;
        }
    }
}

// ---------------------------------------------------------------------------
// Edge kernel: Ea = edge_attr @ W1c.T, fused gather epilogue + relu +
// red.global.add.v4.f32 scatter into g_agg. 128 edges per block.
// ---------------------------------------------------------------------------
__global__ __launch_bounds__(256) void edge_kernel(
    const float* __restrict__ edge_attr, const float* __restrict__ W1,
    const void* __restrict__ ei, const void* __restrict__ batch, int E)
{
    __shared__ __align__(16) float As[16][132];
    __shared__ __align__(16) float Bs[16][132];
    __shared__ int sDst[128], sSrc[128], sGb[128];

    int e0 = blockIdx.x * 128;
    int tid = threadIdx.x;
    if (tid < 128) {
        int ge = e0 + tid;
        int is64 = g_is64;
        if (ge < E) {
            long long s = ld_idx(ei, ge, is64);
            long long d = ld_idx(ei, (long long)E + ge, is64);
            sSrc[tid] = (int)s;
            sDst[tid] = (int)d;
            sGb[tid] = (int)ld_idx(batch, d, is64);
        } else {
            sSrc[tid] = 0; sDst[tid] = 0; sGb[tid] = 0;
        }
    }

    unsigned long long acc[8][4];
    zero_acc(acc);

    tile_gemm(edge_attr, e0, E, W1, 512, 256, acc, As, Bs);

    int tx = tid & 15, ty = tid >> 4;
    int c = tx * 8;
#pragma unroll
    for (int i = 0; i < 8; i++) {
        int e = ty * 8 + i;
        if (e0 + e < E) {
            int d = sDst[e], s = sSrc[e], g = sGb[e];
            const float4* pa = reinterpret_cast<const float4*>(&g_Xa[(size_t)d * 128 + c]);
            const float4* pb = reinterpret_cast<const float4*>(&g_Xb[(size_t)s * 128 + c]);
            const float4* pu = reinterpret_cast<const float4*>(&g_Ue[g * 128 + c]);
            float4 a0 = pa[0], a1 = pa[1];
            float4 b0 = pb[0], b1 = pb[1];
            float4 u0 = pu[0], u1 = pu[1];
            float2 p0 = unpk(acc[i][0]), p1 = unpk(acc[i][1]);
            float2 p2 = unpk(acc[i][2]), p3 = unpk(acc[i][3]);
            float v0 = fmaxf(p0.x + a0.x + b0.x + u0.x, 0.f);
            float v1 = fmaxf(p0.y + a0.y + b0.y + u0.y, 0.f);
            float v2 = fmaxf(p1.x + a0.z + b0.z + u0.z, 0.f);
            float v3 = fmaxf(p1.y + a0.w + b0.w + u0.w, 0.f);
            float v4 = fmaxf(p2.x + a1.x + b1.x + u1.x, 0.f);
            float v5 = fmaxf(p2.y + a1.y + b1.y + u1.y, 0.f);
            float v6 = fmaxf(p3.x + a1.z + b1.z + u1.z, 0.f);
            float v7 = fmaxf(p3.y + a1.w + b1.w + u1.w, 0.f);
            float* dp = &g_agg[(size_t)d * 128 + c];
            red_add_v4(dp,     v0, v1, v2, v3);
            red_add_v4(dp + 4, v4, v5, v6, v7);
        }
    }
}

// ---------------------------------------------------------------------------
// Node kernel: out = relu( Xc + agg @ W2[:,128:256].T + Un[batch] )
// ---------------------------------------------------------------------------
__global__ __launch_bounds__(256) void node_kernel(
    const float* __restrict__ W2, const void* __restrict__ batch,
    float* __restrict__ out, int N)
{
    __shared__ __align__(16) float As[16][132];
    __shared__ __align__(16) float Bs[16][132];

    int n0 = blockIdx.x * 128;
    unsigned long long acc[8][4];
    zero_acc(acc);

    tile_gemm(g_agg, n0, N, W2, 384, 128, acc, As, Bs);

    int tid = threadIdx.x;
    int tx = tid & 15, ty = tid >> 4;
    int c = tx * 8;
    int is64 = g_is64;
#pragma unroll
    for (int i = 0; i < 8; i++) {
        int row = n0 + ty * 8 + i;
        if (row < N) {
            int g = (int)ld_idx(batch, row, is64);
            const float4* pc = reinterpret_cast<const float4*>(&g_Xc[(size_t)row * 128 + c]);
            const float4* pu = reinterpret_cast<const float4*>(&g_Un[g * 128 + c]);
            float4 c0 = pc[0], c1 = pc[1];
            float4 u0 = pu[0], u1 = pu[1];
            float2 p0 = unpk(acc[i][0]), p1 = unpk(acc[i][1]);
            float2 p2 = unpk(acc[i][2]), p3 = unpk(acc[i][3]);
            float4 o0, o1;
            o0.x = fmaxf(p0.x + c0.x + u0.x, 0.f);
            o0.y = fmaxf(p0.y + c0.y + u0.y, 0.f);
            o0.z = fmaxf(p1.x + c0.z + u0.z, 0.f);
            o0.w = fmaxf(p1.y + c0.w + u0.w, 0.f);
            o1.x = fmaxf(p2.x + c1.x + u1.x, 0.f);
            o1.y = fmaxf(p2.y + c1.y + u1.y, 0.f);
            o1.z = fmaxf(p3.x + c1.z + u1.z, 0.f);
            o1.w = fmaxf(p3.y + c1.w + u1.w, 0.f);
            float4* po = reinterpret_cast<float4*>(&out[(size_t)row * 128 + c]);
            po[0] = o0; po[1] = o1;
        }
    }
}

// ---------------------------------------------------------------------------
// Launch. Inputs (metadata order): x, edge_index, edge_attr, u, batch,
//                                  W1, b1, W2, b2. Output: float [N,128].
// ---------------------------------------------------------------------------
extern "C" void kernel_launch(void* const* d_in, const int* in_sizes, int n_in,
                              void* d_out, int out_size) {
    const float* x         = (const float*)d_in[0];
    const void*  ei        = d_in[1];
    const float* edge_attr = (const float*)d_in[2];
    const float* u         = (const float*)d_in[3];
    const void*  batch     = d_in[4];
    const float* W1        = (const float*)d_in[5];
    const float* b1        = (const float*)d_in[6];
    const float* W2        = (const float*)d_in[7];
    const float* b2        = (const float*)d_in[8];
    float* out = (float*)d_out;

    int N = in_sizes[0] / FD;
    int E = in_sizes[2] / FD;
    int G = in_sizes[3] / FD;

    sniff_kernel<<<1, 1>>>((const unsigned int*)ei);

    int n4 = N * (FD / 4);
    zero_kernel<<<(n4 + 255) / 256, 256>>>(n4);

    graph_kernel<<<G, FD>>>(u, W1, b1, W2);

    dim3 pg((N + 127) / 128, 3);
    precompute_kernel<<<pg, 256>>>(x, W1, W2, b2, N);

    edge_kernel<<<(E + 127) / 128, 256>>>(edge_attr, W1, ei, batch, E);

    node_kernel<<<(N + 127) / 128, 256>>>(W2, batch, out, N);
}

// round 8
// speedup vs baseline: 1.3201x; 1.0927x over previous
#include <cuda_runtime.h>
#include <cuda_bf16.h>

// GraphNet NodeModel, algebraically factored:
//   edge_msg = relu( Xa[dst] + Xb[src] + Ea + Ue[batch[dst]] ),  Ea = edge_attr @ W1c.T
//   agg      = segment_sum(edge_msg, dst)        (red.global.add.v4.f32)
//   out      = relu( Xc + agg @ W2b.T + Un[batch] )
// Edge GEMM: legacy mma.sync bf16-split (Ah*Bh + Ah*Bl + Al*Bh), ~2^-17 rel err.
// Other GEMMs: packed fma.rn.f32x2.

#define FD 128
#define MAXN 50000
#define MAXG 64

__device__ float g_Xa[MAXN * FD];    // x @ W1[:,0:128].T      (dest part)
__device__ float g_Xb[MAXN * FD];    // x @ W1[:,128:256].T    (source part)
__device__ float g_Xc[MAXN * FD];    // x @ W2[:,0:128].T + b2
__device__ float g_agg[MAXN * FD];   // segment-summed edge messages
__device__ float g_Ue[MAXG * FD];    // u @ W1[:,384:512].T + b1
__device__ float g_Un[MAXG * FD];    // u @ W2[:,256:384].T
__device__ int   g_is64;             // 1 if indices are int64, 0 if int32

// ---------------- helpers ----------------
__device__ __forceinline__ unsigned long long pack2(float x) {
    unsigned long long r;
    asm("mov.b64 %0, {%1, %1};" : "=l"(r) : "r"(__float_as_uint(x)));
    return r;
}
__device__ __forceinline__ void ffma2(unsigned long long& d,
                                      unsigned long long a,
                                      unsigned long long b) {
    asm("fma.rn.f32x2 %0, %1, %2, %0;" : "+l"(d) : "l"(a), "l"(b));
}
__device__ __forceinline__ float2 unpk(unsigned long long v) {
    float2 f;
    asm("mov.b64 {%0, %1}, %2;" : "=f"(f.x), "=f"(f.y) : "l"(v));
    return f;
}
__device__ __forceinline__ void red_add_v4(float* p, float a, float b,
                                           float c, float d) {
    unsigned long long gp = (unsigned long long)__cvta_generic_to_global(p);
    asm volatile("red.global.add.v4.f32 [%0], {%1, %2, %3, %4};"
                 :: "l"(gp), "f"(a), "f"(b), "f"(c), "f"(d) : "memory");
}
__device__ __forceinline__ long long ld_idx(const void* p, long long i, int is64) {
    if (is64) return ((const long long*)p)[i];
    return (long long)((const int*)p)[i];
}

// Split float2 -> bf16x2 hi (return) and bf16x2 lo (residual). Low half = .x.
__device__ __forceinline__ unsigned int bfsplit2(float2 f, unsigned int& lo) {
    unsigned int hi;
    asm("cvt.rn.bf16x2.f32 %0, %1, %2;" : "=r"(hi) : "f"(f.y), "f"(f.x));
    float rx = f.x - __uint_as_float(hi << 16);
    float ry = f.y - __uint_as_float(hi & 0xffff0000u);
    asm("cvt.rn.bf16x2.f32 %0, %1, %2;" : "=r"(lo) : "f"(ry), "f"(rx));
    return hi;
}

// m16n8k16 row.col bf16 MMA, fp32 accumulate (base ISA, compiles for sm_100).
__device__ __forceinline__ void mma_bf16(float& c0, float& c1, float& c2, float& c3,
                                         unsigned int a0, unsigned int a1,
                                         unsigned int a2, unsigned int a3,
                                         unsigned int b0, unsigned int b1) {
    asm volatile(
        "mma.sync.aligned.m16n8k16.row.col.f32.bf16.bf16.f32 "
        "{%0,%1,%2,%3}, {%4,%5,%6,%7}, {%8,%9}, {%0,%1,%2,%3};"
        : "+f"(c0), "+f"(c1), "+f"(c2), "+f"(c3)
        : "r"(a0), "r"(a1), "r"(a2), "r"(a3), "r"(b0), "r"(b1));
}

// ---------------------------------------------------------------------------
// Detect index dtype: int64 values < 2^31 have all-zero odd 32-bit words.
// ---------------------------------------------------------------------------
__global__ void sniff_kernel(const unsigned int* __restrict__ ei) {
    int is64 = 1;
#pragma unroll 1
    for (int k = 1; k < 129; k += 2) {
        if (ei[k] != 0u) { is64 = 0; break; }
    }
    g_is64 = is64;
}

__global__ void zero_kernel(int n4) {
    int i = blockIdx.x * blockDim.x + threadIdx.x;
    if (i < n4)
        reinterpret_cast<float4*>(g_agg)[i] = make_float4(0.f, 0.f, 0.f, 0.f);
}

// ---------------------------------------------------------------------------
// Per-graph GEMMs (tiny: 64 x 128 each). Block = one graph, 128 threads.
// ---------------------------------------------------------------------------
__global__ void graph_kernel(const float* __restrict__ u,
                             const float* __restrict__ W1,
                             const float* __restrict__ b1,
                             const float* __restrict__ W2) {
    __shared__ float su[FD];
    int g = blockIdx.x;
    int o = threadIdx.x;
    su[o] = u[g * FD + o];
    __syncthreads();
    float a1 = b1[o];
    float a2 = 0.f;
    const float* w1r = W1 + o * 512 + 384;
    const float* w2r = W2 + o * 384 + 256;
#pragma unroll 8
    for (int k = 0; k < FD; k++) {
        a1 = fmaf(su[k], w1r[k], a1);
        a2 = fmaf(su[k], w2r[k], a2);
    }
    g_Ue[g * FD + o] = a1;
    g_Un[g * FD + o] = a2;
}

// ---------------------------------------------------------------------------
// FFMA2 tile GEMM (precompute/node): 128x128xK=128, 256 threads.
// ---------------------------------------------------------------------------
__device__ __forceinline__ void tile_gemm(
    const float* __restrict__ A, int rowBase, int M,
    const float* __restrict__ W, int ldw, int off,
    unsigned long long (&acc)[8][4], float (*As)[132], float (*Bs)[132])
{
    const int tid = threadIdx.x;
    const int le = tid & 127;
    const int lq = (tid >> 7) << 3;
    const int tx = tid & 15;
    const int ty = tid >> 4;

#pragma unroll 1
    for (int k0 = 0; k0 < 128; k0 += 16) {
        float4 v0, v1;
        int row = rowBase + le;
        if (row < M) {
            const float4* p = reinterpret_cast<const float4*>(
                A + (size_t)row * 128 + k0 + lq);
            v0 = p[0]; v1 = p[1];
        } else {
            v0 = make_float4(0.f, 0.f, 0.f, 0.f); v1 = v0;
        }
        const float4* q = reinterpret_cast<const float4*>(
            W + (size_t)le * ldw + off + k0 + lq);
        float4 w0 = q[0], w1 = q[1];

        __syncthreads();
        As[lq + 0][le] = v0.x; As[lq + 1][le] = v0.y;
        As[lq + 2][le] = v0.z; As[lq + 3][le] = v0.w;
        As[lq + 4][le] = v1.x; As[lq + 5][le] = v1.y;
        As[lq + 6][le] = v1.z; As[lq + 7][le] = v1.w;
        Bs[lq + 0][le] = w0.x; Bs[lq + 1][le] = w0.y;
        Bs[lq + 2][le] = w0.z; Bs[lq + 3][le] = w0.w;
        Bs[lq + 4][le] = w1.x; Bs[lq + 5][le] = w1.y;
        Bs[lq + 6][le] = w1.z; Bs[lq + 7][le] = w1.w;
        __syncthreads();

#pragma unroll
        for (int kk = 0; kk < 16; kk++) {
            float4 a0 = *reinterpret_cast<const float4*>(&As[kk][ty * 8]);
            float4 a1 = *reinterpret_cast<const float4*>(&As[kk][ty * 8 + 4]);
            ulonglong2 b01 = *reinterpret_cast<const ulonglong2*>(&Bs[kk][tx * 8]);
            ulonglong2 b23 = *reinterpret_cast<const ulonglong2*>(&Bs[kk][tx * 8 + 4]);
            unsigned long long av[8];
            av[0] = pack2(a0.x); av[1] = pack2(a0.y);
            av[2] = pack2(a0.z); av[3] = pack2(a0.w);
            av[4] = pack2(a1.x); av[5] = pack2(a1.y);
            av[6] = pack2(a1.z); av[7] = pack2(a1.w);
            unsigned long long bv[4] = {b01.x, b01.y, b23.x, b23.y};
#pragma unroll
            for (int i = 0; i < 8; i++)
#pragma unroll
                for (int j = 0; j < 4; j++)
                    ffma2(acc[i][j], av[i], bv[j]);
        }
    }
    __syncthreads();
}

__device__ __forceinline__ void zero_acc(unsigned long long (&acc)[8][4]) {
#pragma unroll
    for (int i = 0; i < 8; i++)
#pragma unroll
        for (int j = 0; j < 4; j++) acc[i][j] = 0ull;
}

// ---------------------------------------------------------------------------
// Precompute Xa / Xb / Xc: grid.y selects which product.
// ---------------------------------------------------------------------------
__global__ __launch_bounds__(256) void precompute_kernel(
    const float* __restrict__ x, const float* __restrict__ W1,
    const float* __restrict__ W2, const float* __restrict__ b2, int N)
{
    __shared__ __align__(16) float As[16][132];
    __shared__ __align__(16) float Bs[16][132];

    const float* W; int ldw, off; const float* bias; float* C;
    int which = blockIdx.y;
    if (which == 0)      { W = W1; ldw = 512; off = 0;   bias = 0;   C = g_Xa; }
    else if (which == 1) { W = W1; ldw = 512; off = 128; bias = 0;   C = g_Xb; }
    else                 { W = W2; ldw = 384; off = 0;   bias = b2;  C = g_Xc; }

    unsigned long long acc[8][4];
    zero_acc(acc);

    int m0 = blockIdx.x * 128;
    tile_gemm(x, m0, N, W, ldw, off, acc, As, Bs);

    int tx = threadIdx.x & 15, ty = threadIdx.x >> 4;
    int c = tx * 8;
    float bb[8] = {0.f, 0.f, 0.f, 0.f, 0.f, 0.f, 0.f, 0.f};
    if (bias) {
        const float4* pb = reinterpret_cast<const float4*>(bias + c);
        float4 q0 = pb[0], q1 = pb[1];
        bb[0] = q0.x; bb[1] = q0.y; bb[2] = q0.z; bb[3] = q0.w;
        bb[4] = q1.x; bb[5] = q1.y; bb[6] = q1.z; bb[7] = q1.w;
    }
#pragma unroll
    for (int i = 0; i < 8; i++) {
        int row = m0 + ty * 8 + i;
        if (row < N) {
            float2 p0 = unpk(acc[i][0]), p1 = unpk(acc[i][1]);
            float2 p2 = unpk(acc[i][2]), p3 = unpk(acc[i][3]);
            float4 o0 = make_float4(p0.x + bb[0], p0.y + bb[1],
                                    p1.x + bb[2], p1.y + bb[3]);
            float4 o1 = make_float4(p2.x + bb[4], p2.y + bb[5],
                                    p3.x + bb[6], p3.y + bb[7]);
            float4* po = reinterpret_cast<float4*>(&C[(size_t)row * 128 + c]);
            po[0] = o0; po[1] = o1;
        }
    }
}

// ---------------------------------------------------------------------------
// Edge kernel (mma.sync bf16-split): 128 edges per block, 8 warps.
// Warp w owns rows 16w..16w+15. A frags built straight from gmem fp32.
// B = W1[:,256:384] staged to smem as bf16 hi/lo, row stride 136 (conflict-free
// b-frag loads: bank = lane). C staged through smem (aliases B) for a coherent
// float4 gather + relu + red.global.add.v4 epilogue.
// ---------------------------------------------------------------------------
#define BSTR 136                       // bf16 elements per B smem row
#define SM_B   2048                    // byte offset of Bhi
#define SM_BSZ (128 * BSTR * 2)        // 34816 bytes per B array
#define SM_EDGE_TOTAL (SM_B + 2 * SM_BSZ)  // 71680 bytes

__global__ __launch_bounds__(256, 2)
void edge_mma_kernel(const float* __restrict__ edge_attr,
                     const float* __restrict__ W1,
                     const void* __restrict__ ei,
                     const void* __restrict__ batch, int E)
{
    extern __shared__ __align__(16) char smem[];
    int* sDst = (int*)smem;
    int* sSrc = sDst + 128;
    int* sGb  = sSrc + 128;
    __nv_bfloat16* Bhi = (__nv_bfloat16*)(smem + SM_B);
    __nv_bfloat16* Blo = (__nv_bfloat16*)(smem + SM_B + SM_BSZ);
    float* Cbuf = (float*)(smem + SM_B);          // [128][132], aliases B

    const int tid = threadIdx.x;
    const int wid = tid >> 5;
    const int lane = tid & 31;
    const long long e0 = (long long)blockIdx.x * 128;

    // indices
    if (tid < 128) {
        int is64 = g_is64;
        long long ge = e0 + tid;
        if (ge < E) {
            sSrc[tid] = (int)ld_idx(ei, ge, is64);
            long long d = ld_idx(ei, (long long)E + ge, is64);
            sDst[tid] = (int)d;
            sGb[tid]  = (int)ld_idx(batch, d, is64);
        } else {
            sSrc[tid] = 0; sDst[tid] = 0; sGb[tid] = 0;
        }
    }

    // stage B = W1c (128x128) as bf16 hi/lo
#pragma unroll 2
    for (int g = tid; g < 128 * 16; g += 256) {
        int r = g >> 4;
        int c0 = (g & 15) << 3;
        const float2* p = reinterpret_cast<const float2*>(W1 + (size_t)r * 512 + 256 + c0);
        unsigned int h[4], l[4];
#pragma unroll
        for (int q = 0; q < 4; q++) h[q] = bfsplit2(p[q], l[q]);
        *reinterpret_cast<uint4*>(Bhi + r * BSTR + c0) = make_uint4(h[0], h[1], h[2], h[3]);
        *reinterpret_cast<uint4*>(Blo + r * BSTR + c0) = make_uint4(l[0], l[1], l[2], l[3]);
    }
    __syncthreads();

    // ---- mma mainloop ----
    const int rloc = (lane >> 2);                 // 0..7
    const long long ge0 = e0 + wid * 16 + rloc;
    const long long ge1 = ge0 + 8;
    const bool v0 = ge0 < E, v1 = ge1 < E;
    const float* A0 = edge_attr + ge0 * 128 + (lane & 3) * 2;
    const float* A1 = edge_attr + ge1 * 128 + (lane & 3) * 2;

    float acc[16][4];
#pragma unroll
    for (int t = 0; t < 16; t++)
#pragma unroll
        for (int j = 0; j < 4; j++) acc[t][j] = 0.f;

    const float2 Z2 = make_float2(0.f, 0.f);
    float2 cur[4];
    cur[0] = v0 ? *reinterpret_cast<const float2*>(A0)     : Z2;
    cur[1] = v1 ? *reinterpret_cast<const float2*>(A1)     : Z2;
    cur[2] = v0 ? *reinterpret_cast<const float2*>(A0 + 8) : Z2;
    cur[3] = v1 ? *reinterpret_cast<const float2*>(A1 + 8) : Z2;

#pragma unroll
    for (int kc = 0; kc < 8; kc++) {
        const int k0 = kc * 16;
        float2 nxt[4];
        if (kc < 7) {
            nxt[0] = v0 ? *reinterpret_cast<const float2*>(A0 + k0 + 16) : Z2;
            nxt[1] = v1 ? *reinterpret_cast<const float2*>(A1 + k0 + 16) : Z2;
            nxt[2] = v0 ? *reinterpret_cast<const float2*>(A0 + k0 + 24) : Z2;
            nxt[3] = v1 ? *reinterpret_cast<const float2*>(A1 + k0 + 24) : Z2;
        } else {
            nxt[0] = Z2; nxt[1] = Z2; nxt[2] = Z2; nxt[3] = Z2;
        }

        unsigned int ahi[4], alo[4];
#pragma unroll
        for (int q = 0; q < 4; q++) ahi[q] = bfsplit2(cur[q], alo[q]);

        const int boff = rloc * BSTR + k0 + (lane & 3) * 2;
#pragma unroll
        for (int nt = 0; nt < 16; nt++) {
            const __nv_bfloat16* ph = Bhi + nt * 8 * BSTR + boff;
            const __nv_bfloat16* pl = Blo + nt * 8 * BSTR + boff;
            unsigned int bh0 = *reinterpret_cast<const unsigned int*>(ph);
            unsigned int bh1 = *reinterpret_cast<const unsigned int*>(ph + 8);
            unsigned int bl0 = *reinterpret_cast<const unsigned int*>(pl);
            unsigned int bl1 = *reinterpret_cast<const unsigned int*>(pl + 8);
            mma_bf16(acc[nt][0], acc[nt][1], acc[nt][2], acc[nt][3],
                     ahi[0], ahi[1], ahi[2], ahi[3], bh0, bh1);
            mma_bf16(acc[nt][0], acc[nt][1], acc[nt][2], acc[nt][3],
                     ahi[0], ahi[1], ahi[2], ahi[3], bl0, bl1);
            mma_bf16(acc[nt][0], acc[nt][1], acc[nt][2], acc[nt][3],
                     alo[0], alo[1], alo[2], alo[3], bh0, bh1);
        }
        cur[0] = nxt[0]; cur[1] = nxt[1]; cur[2] = nxt[2]; cur[3] = nxt[3];
    }

    // ---- stage C to smem (B no longer needed) ----
    __syncthreads();
    {
        const int rbase = wid * 16 + rloc;
        const int cb = (lane & 3) * 2;
#pragma unroll
        for (int nt = 0; nt < 16; nt++) {
            float* p0 = Cbuf + rbase * 132 + nt * 8 + cb;
            *reinterpret_cast<float2*>(p0)           = make_float2(acc[nt][0], acc[nt][1]);
            *reinterpret_cast<float2*>(p0 + 8 * 132) = make_float2(acc[nt][2], acc[nt][3]);
        }
    }
    __syncthreads();

    // ---- epilogue: gather + relu + scatter-add (2 threads per edge) ----
    {
        const int el = tid >> 1;
        const int cb = (tid & 1) * 64;
        if (e0 + el < E) {
            int d = sDst[el], s = sSrc[el], gb = sGb[el];
            const float* xa = g_Xa + (size_t)d * 128 + cb;
            const float* xb = g_Xb + (size_t)s * 128 + cb;
            const float* ue = g_Ue + gb * 128 + cb;
            float* dp = g_agg + (size_t)d * 128 + cb;
            const float* cr = Cbuf + el * 132 + cb;
#pragma unroll
            for (int j = 0; j < 16; j++) {
                int c = j * 4;
                float4 m  = *reinterpret_cast<const float4*>(cr + c);
                float4 a  = *reinterpret_cast<const float4*>(xa + c);
                float4 b  = *reinterpret_cast<const float4*>(xb + c);
                float4 uu = *reinterpret_cast<const float4*>(ue + c);
                float w0 = fmaxf(m.x + a.x + b.x + uu.x, 0.f);
                float w1 = fmaxf(m.y + a.y + b.y + uu.y, 0.f);
                float w2 = fmaxf(m.z + a.z + b.z + uu.z, 0.f);
                float w3 = fmaxf(m.w + a.w + b.w + uu.w, 0.f);
                red_add_v4(dp + c, w0, w1, w2, w3);
            }
        }
    }
}

// ---------------------------------------------------------------------------
// Node kernel: out = relu( Xc + agg @ W2[:,128:256].T + Un[batch] )
// ---------------------------------------------------------------------------
__global__ __launch_bounds__(256) void node_kernel(
    const float* __restrict__ W2, const void* __restrict__ batch,
    float* __restrict__ out, int N)
{
    __shared__ __align__(16) float As[16][132];
    __shared__ __align__(16) float Bs[16][132];

    int n0 = blockIdx.x * 128;
    unsigned long long acc[8][4];
    zero_acc(acc);

    tile_gemm(g_agg, n0, N, W2, 384, 128, acc, As, Bs);

    int tid = threadIdx.x;
    int tx = tid & 15, ty = tid >> 4;
    int c = tx * 8;
    int is64 = g_is64;
#pragma unroll
    for (int i = 0; i < 8; i++) {
        int row = n0 + ty * 8 + i;
        if (row < N) {
            int g = (int)ld_idx(batch, row, is64);
            const float4* pc = reinterpret_cast<const float4*>(&g_Xc[(size_t)row * 128 + c]);
            const float4* pu = reinterpret_cast<const float4*>(&g_Un[g * 128 + c]);
            float4 c0 = pc[0], c1 = pc[1];
            float4 u0 = pu[0], u1 = pu[1];
            float2 p0 = unpk(acc[i][0]), p1 = unpk(acc[i][1]);
            float2 p2 = unpk(acc[i][2]), p3 = unpk(acc[i][3]);
            float4 o0, o1;
            o0.x = fmaxf(p0.x + c0.x + u0.x, 0.f);
            o0.y = fmaxf(p0.y + c0.y + u0.y, 0.f);
            o0.z = fmaxf(p1.x + c0.z + u0.z, 0.f);
            o0.w = fmaxf(p1.y + c0.w + u0.w, 0.f);
            o1.x = fmaxf(p2.x + c1.x + u1.x, 0.f);
            o1.y = fmaxf(p2.y + c1.y + u1.y, 0.f);
            o1.z = fmaxf(p3.x + c1.z + u1.z, 0.f);
            o1.w = fmaxf(p3.y + c1.w + u1.w, 0.f);
            float4* po = reinterpret_cast<float4*>(&out[(size_t)row * 128 + c]);
            po[0] = o0; po[1] = o1;
        }
    }
}

// ---------------------------------------------------------------------------
// Launch. Inputs (metadata order): x, edge_index, edge_attr, u, batch,
//                                  W1, b1, W2, b2. Output: float [N,128].
// ---------------------------------------------------------------------------
extern "C" void kernel_launch(void* const* d_in, const int* in_sizes, int n_in,
                              void* d_out, int out_size) {
    const float* x         = (const float*)d_in[0];
    const void*  ei        = d_in[1];
    const float* edge_attr = (const float*)d_in[2];
    const float* u         = (const float*)d_in[3];
    const void*  batch     = d_in[4];
    const float* W1        = (const float*)d_in[5];
    const float* b1        = (const float*)d_in[6];
    const float* W2        = (const float*)d_in[7];
    const float* b2        = (const float*)d_in[8];
    float* out = (float*)d_out;

    int N = in_sizes[0] / FD;
    int E = in_sizes[2] / FD;
    int G = in_sizes[3] / FD;

    cudaFuncSetAttribute(edge_mma_kernel,
                         cudaFuncAttributeMaxDynamicSharedMemorySize, SM_EDGE_TOTAL);

    sniff_kernel<<<1, 1>>>((const unsigned int*)ei);

    int n4 = N * (FD / 4);
    zero_kernel<<<(n4 + 255) / 256, 256>>>(n4);

    graph_kernel<<<G, FD>>>(u, W1, b1, W2);

    dim3 pg((N + 127) / 128, 3);
    precompute_kernel<<<pg, 256>>>(x, W1, W2, b2, N);

    edge_mma_kernel<<<(E + 127) / 128, 256, SM_EDGE_TOTAL>>>(edge_attr, W1, ei, batch, E);

    node_kernel<<<(N + 127) / 128, 256>>>(W2, batch, out, N);
}

// round 9
// speedup vs baseline: 1.5645x; 1.1852x over previous
#include <cuda_runtime.h>
#include <cuda_fp16.h>

// GraphNet NodeModel, algebraically factored:
//   edge_msg = relu( Xa[dst] + Xb[src] + Ea + Ue[batch[dst]] ),  Ea = edge_attr @ W1c.T
//   agg      = segment_sum(edge_msg, dst)        (red.global.add.v4.f32)
//   out      = relu( Xc + agg @ W2b.T + Un[batch] )
// Edge + precompute GEMMs: single-pass fp16 mma.sync (fp32 accumulate).
// Node/graph GEMMs: fp32 (packed fma.rn.f32x2).

#define FD 128
#define MAXN 50000
#define MAXG 64

__device__ float g_Xa[MAXN * FD];    // x @ W1[:,0:128].T      (dest part)
__device__ float g_Xb[MAXN * FD];    // x @ W1[:,128:256].T    (source part)
__device__ float g_Xc[MAXN * FD];    // x @ W2[:,0:128].T + b2
__device__ float g_agg[MAXN * FD];   // segment-summed edge messages
__device__ float g_Ue[MAXG * FD];    // u @ W1[:,384:512].T + b1
__device__ float g_Un[MAXG * FD];    // u @ W2[:,256:384].T
__device__ int   g_is64;             // 1 if indices are int64, 0 if int32

// ---------------- helpers ----------------
__device__ __forceinline__ unsigned long long pack2(float x) {
    unsigned long long r;
    asm("mov.b64 %0, {%1, %1};" : "=l"(r) : "r"(__float_as_uint(x)));
    return r;
}
__device__ __forceinline__ void ffma2(unsigned long long& d,
                                      unsigned long long a,
                                      unsigned long long b) {
    asm("fma.rn.f32x2 %0, %1, %2, %0;" : "+l"(d) : "l"(a), "l"(b));
}
__device__ __forceinline__ float2 unpk(unsigned long long v) {
    float2 f;
    asm("mov.b64 {%0, %1}, %2;" : "=f"(f.x), "=f"(f.y) : "l"(v));
    return f;
}
__device__ __forceinline__ void red_add_v4(float* p, float a, float b,
                                           float c, float d) {
    unsigned long long gp = (unsigned long long)__cvta_generic_to_global(p);
    asm volatile("red.global.add.v4.f32 [%0], {%1, %2, %3, %4};"
                 :: "l"(gp), "f"(a), "f"(b), "f"(c), "f"(d) : "memory");
}
__device__ __forceinline__ long long ld_idx(const void* p, long long i, int is64) {
    if (is64) return ((const long long*)p)[i];
    return (long long)((const int*)p)[i];
}
// float2 -> packed f16x2 (low half = .x)
__device__ __forceinline__ unsigned int f16pack(float2 f) {
    unsigned int h;
    asm("cvt.rn.f16x2.f32 %0, %1, %2;" : "=r"(h) : "f"(f.y), "f"(f.x));
    return h;
}
// m16n8k16 row.col fp16 MMA, fp32 accumulate (base ISA, ok for compute_100).
__device__ __forceinline__ void mma_f16(float& c0, float& c1, float& c2, float& c3,
                                        unsigned int a0, unsigned int a1,
                                        unsigned int a2, unsigned int a3,
                                        unsigned int b0, unsigned int b1) {
    asm volatile(
        "mma.sync.aligned.m16n8k16.row.col.f32.f16.f16.f32 "
        "{%0,%1,%2,%3}, {%4,%5,%6,%7}, {%8,%9}, {%0,%1,%2,%3};"
        : "+f"(c0), "+f"(c1), "+f"(c2), "+f"(c3)
        : "r"(a0), "r"(a1), "r"(a2), "r"(a3), "r"(b0), "r"(b1));
}

// ---------------------------------------------------------------------------
// Detect index dtype: int64 values < 2^31 have all-zero odd 32-bit words.
// ---------------------------------------------------------------------------
__global__ void sniff_kernel(const unsigned int* __restrict__ ei) {
    int is64 = 1;
#pragma unroll 1
    for (int k = 1; k < 129; k += 2) {
        if (ei[k] != 0u) { is64 = 0; break; }
    }
    g_is64 = is64;
}

__global__ void zero_kernel(int n4) {
    int i = blockIdx.x * blockDim.x + threadIdx.x;
    if (i < n4)
        reinterpret_cast<float4*>(g_agg)[i] = make_float4(0.f, 0.f, 0.f, 0.f);
}

// ---------------------------------------------------------------------------
// Per-graph GEMMs (tiny: 64 x 128 each). Block = one graph, 128 threads. fp32.
// ---------------------------------------------------------------------------
__global__ void graph_kernel(const float* __restrict__ u,
                             const float* __restrict__ W1,
                             const float* __restrict__ b1,
                             const float* __restrict__ W2) {
    __shared__ float su[FD];
    int g = blockIdx.x;
    int o = threadIdx.x;
    su[o] = u[g * FD + o];
    __syncthreads();
    float a1 = b1[o];
    float a2 = 0.f;
    const float* w1r = W1 + o * 512 + 384;
    const float* w2r = W2 + o * 384 + 256;
#pragma unroll 8
    for (int k = 0; k < FD; k++) {
        a1 = fmaf(su[k], w1r[k], a1);
        a2 = fmaf(su[k], w2r[k], a2);
    }
    g_Ue[g * FD + o] = a1;
    g_Un[g * FD + o] = a2;
}

// ---------------------------------------------------------------------------
// Shared fp16 warp-tile mainloop pieces.
// B smem: 128 rows (out-cols) x BSTR fp16, row r holds W[r][off..off+127].
// b-frag loads are conflict-free: bank = (68r + 2(lane&3)) mod 32 spans lanes.
// ---------------------------------------------------------------------------
#define BSTR 136
#define SM_B   2048                      // byte offset of B in dynamic smem
#define SM_BSZ (128 * BSTR * 2)          // 34816 bytes (fp16)
#define SM_EDGE_TOTAL (SM_B + 128 * 132 * 4)   // idx + Cbuf(aliases B): 69632

// Stage one 128x128 weight block as fp16 into smem (256 threads).
__device__ __forceinline__ void stage_B(__half* Bh, const float* __restrict__ W,
                                        int ldw, int off) {
#pragma unroll 2
    for (int g = threadIdx.x; g < 128 * 16; g += 256) {
        int r = g >> 4;
        int c0 = (g & 15) << 3;
        const float2* p = reinterpret_cast<const float2*>(W + (size_t)r * ldw + off + c0);
        unsigned int h0 = f16pack(p[0]);
        unsigned int h1 = f16pack(p[1]);
        unsigned int h2 = f16pack(p[2]);
        unsigned int h3 = f16pack(p[3]);
        *reinterpret_cast<uint4*>(Bh + r * BSTR + c0) = make_uint4(h0, h1, h2, h3);
    }
}

// fp16 mainloop: rows r0 (=base+lane/4) and r0+8 of A (fp32, row stride 128),
// accumulating acc[16][4] (cols nt*8 + (lane&3)*2, +1).
__device__ __forceinline__ void mma_mainloop(
    const float* __restrict__ A, long long r0g, long long r1g, long long M,
    const __half* Bh, int lane, float (&acc)[16][4])
{
    const bool v0 = r0g < M, v1 = r1g < M;
    const float* A0 = A + r0g * 128 + (lane & 3) * 2;
    const float* A1 = A + r1g * 128 + (lane & 3) * 2;
    const float2 Z2 = make_float2(0.f, 0.f);
    float2 cur[4];
    cur[0] = v0 ? *reinterpret_cast<const float2*>(A0)     : Z2;
    cur[1] = v1 ? *reinterpret_cast<const float2*>(A1)     : Z2;
    cur[2] = v0 ? *reinterpret_cast<const float2*>(A0 + 8) : Z2;
    cur[3] = v1 ? *reinterpret_cast<const float2*>(A1 + 8) : Z2;

#pragma unroll
    for (int kc = 0; kc < 8; kc++) {
        const int k0 = kc * 16;
        float2 nxt[4];
        if (kc < 7) {
            nxt[0] = v0 ? *reinterpret_cast<const float2*>(A0 + k0 + 16) : Z2;
            nxt[1] = v1 ? *reinterpret_cast<const float2*>(A1 + k0 + 16) : Z2;
            nxt[2] = v0 ? *reinterpret_cast<const float2*>(A0 + k0 + 24) : Z2;
            nxt[3] = v1 ? *reinterpret_cast<const float2*>(A1 + k0 + 24) : Z2;
        } else {
            nxt[0] = Z2; nxt[1] = Z2; nxt[2] = Z2; nxt[3] = Z2;
        }
        unsigned int a0 = f16pack(cur[0]);
        unsigned int a1 = f16pack(cur[1]);
        unsigned int a2 = f16pack(cur[2]);
        unsigned int a3 = f16pack(cur[3]);

        const int boff = (lane >> 2) * BSTR + k0 + (lane & 3) * 2;
#pragma unroll
        for (int nt = 0; nt < 16; nt++) {
            const __half* ph = Bh + nt * 8 * BSTR + boff;
            unsigned int b0 = *reinterpret_cast<const unsigned int*>(ph);
            unsigned int b1 = *reinterpret_cast<const unsigned int*>(ph + 8);
            mma_f16(acc[nt][0], acc[nt][1], acc[nt][2], acc[nt][3],
                    a0, a1, a2, a3, b0, b1);
        }
        cur[0] = nxt[0]; cur[1] = nxt[1]; cur[2] = nxt[2]; cur[3] = nxt[3];
    }
}

// ---------------------------------------------------------------------------
// Precompute Xa / Xb / Xc via fp16 mma: grid.y selects the product.
// ---------------------------------------------------------------------------
__global__ __launch_bounds__(256, 2)
void precompute_mma_kernel(const float* __restrict__ x,
                           const float* __restrict__ W1,
                           const float* __restrict__ W2,
                           const float* __restrict__ b2, int N)
{
    extern __shared__ __align__(16) char smem[];
    __half* Bh = (__half*)smem;

    const float* W; int ldw, off; const float* bias; float* C;
    int which = blockIdx.y;
    if (which == 0)      { W = W1; ldw = 512; off = 0;   bias = 0;   C = g_Xa; }
    else if (which == 1) { W = W1; ldw = 512; off = 128; bias = 0;   C = g_Xb; }
    else                 { W = W2; ldw = 384; off = 0;   bias = b2;  C = g_Xc; }

    stage_B(Bh, W, ldw, off);
    __syncthreads();

    const int tid = threadIdx.x;
    const int wid = tid >> 5;
    const int lane = tid & 31;
    const long long m0 = (long long)blockIdx.x * 128;
    const long long r0 = m0 + wid * 16 + (lane >> 2);
    const long long r1 = r0 + 8;

    float acc[16][4];
#pragma unroll
    for (int t = 0; t < 16; t++)
#pragma unroll
        for (int j = 0; j < 4; j++) acc[t][j] = 0.f;

    mma_mainloop(x, r0, r1, N, Bh, lane, acc);

    const int cb = (lane & 3) * 2;
#pragma unroll
    for (int nt = 0; nt < 16; nt++) {
        int c = nt * 8 + cb;
        float bx = 0.f, by = 0.f;
        if (bias) { bx = bias[c]; by = bias[c + 1]; }
        if (r0 < N)
            *reinterpret_cast<float2*>(C + r0 * 128 + c) =
                make_float2(acc[nt][0] + bx, acc[nt][1] + by);
        if (r1 < N)
            *reinterpret_cast<float2*>(C + r1 * 128 + c) =
                make_float2(acc[nt][2] + bx, acc[nt][3] + by);
    }
}

// ---------------------------------------------------------------------------
// Edge kernel: Ea = edge_attr @ W1c.T via fp16 mma; C staged through smem
// (aliases B) for a coherent float4 gather + relu + red.global.add.v4 epilogue.
// 128 edges per block, 8 warps.
// ---------------------------------------------------------------------------
__global__ __launch_bounds__(256, 2)
void edge_mma_kernel(const float* __restrict__ edge_attr,
                     const float* __restrict__ W1,
                     const void* __restrict__ ei,
                     const void* __restrict__ batch, int E)
{
    extern __shared__ __align__(16) char smem[];
    int* sDst = (int*)smem;
    int* sSrc = sDst + 128;
    int* sGb  = sSrc + 128;
    __half* Bh = (__half*)(smem + SM_B);
    float* Cbuf = (float*)(smem + SM_B);          // [128][132], aliases B

    const int tid = threadIdx.x;
    const int wid = tid >> 5;
    const int lane = tid & 31;
    const long long e0 = (long long)blockIdx.x * 128;

    // indices
    if (tid < 128) {
        int is64 = g_is64;
        long long ge = e0 + tid;
        if (ge < E) {
            sSrc[tid] = (int)ld_idx(ei, ge, is64);
            long long d = ld_idx(ei, (long long)E + ge, is64);
            sDst[tid] = (int)d;
            sGb[tid]  = (int)ld_idx(batch, d, is64);
        } else {
            sSrc[tid] = 0; sDst[tid] = 0; sGb[tid] = 0;
        }
    }

    stage_B(Bh, W1, 512, 256);   // W1c = W1[:,256:384]
    __syncthreads();

    const long long r0 = e0 + wid * 16 + (lane >> 2);
    const long long r1 = r0 + 8;

    float acc[16][4];
#pragma unroll
    for (int t = 0; t < 16; t++)
#pragma unroll
        for (int j = 0; j < 4; j++) acc[t][j] = 0.f;

    mma_mainloop(edge_attr, r0, r1, E, Bh, lane, acc);

    // ---- stage C to smem (B no longer needed) ----
    __syncthreads();
    {
        const int rbase = wid * 16 + (lane >> 2);
        const int cb = (lane & 3) * 2;
#pragma unroll
        for (int nt = 0; nt < 16; nt++) {
            float* p0 = Cbuf + rbase * 132 + nt * 8 + cb;
            *reinterpret_cast<float2*>(p0)           = make_float2(acc[nt][0], acc[nt][1]);
            *reinterpret_cast<float2*>(p0 + 8 * 132) = make_float2(acc[nt][2], acc[nt][3]);
        }
    }
    __syncthreads();

    // ---- epilogue: gather + relu + scatter-add (2 threads per edge) ----
    {
        const int el = tid >> 1;
        const int cb = (tid & 1) * 64;
        if (e0 + el < E) {
            int d = sDst[el], s = sSrc[el], gb = sGb[el];
            const float* xa = g_Xa + (size_t)d * 128 + cb;
            const float* xb = g_Xb + (size_t)s * 128 + cb;
            const float* ue = g_Ue + gb * 128 + cb;
            float* dp = g_agg + (size_t)d * 128 + cb;
            const float* cr = Cbuf + el * 132 + cb;
#pragma unroll
            for (int j = 0; j < 16; j++) {
                int c = j * 4;
                float4 m  = *reinterpret_cast<const float4*>(cr + c);
                float4 a  = *reinterpret_cast<const float4*>(xa + c);
                float4 b  = *reinterpret_cast<const float4*>(xb + c);
                float4 uu = *reinterpret_cast<const float4*>(ue + c);
                float w0 = fmaxf(m.x + a.x + b.x + uu.x, 0.f);
                float w1 = fmaxf(m.y + a.y + b.y + uu.y, 0.f);
                float w2 = fmaxf(m.z + a.z + b.z + uu.z, 0.f);
                float w3 = fmaxf(m.w + a.w + b.w + uu.w, 0.f);
                red_add_v4(dp + c, w0, w1, w2, w3);
            }
        }
    }
}

// ---------------------------------------------------------------------------
// FFMA2 tile GEMM (node kernel): 128x128xK=128, 256 threads. fp32 exact.
// ---------------------------------------------------------------------------
__device__ __forceinline__ void tile_gemm(
    const float* __restrict__ A, int rowBase, int M,
    const float* __restrict__ W, int ldw, int off,
    unsigned long long (&acc)[8][4], float (*As)[132], float (*Bs)[132])
{
    const int tid = threadIdx.x;
    const int le = tid & 127;
    const int lq = (tid >> 7) << 3;
    const int tx = tid & 15;
    const int ty = tid >> 4;

#pragma unroll 1
    for (int k0 = 0; k0 < 128; k0 += 16) {
        float4 v0, v1;
        int row = rowBase + le;
        if (row < M) {
            const float4* p = reinterpret_cast<const float4*>(
                A + (size_t)row * 128 + k0 + lq);
            v0 = p[0]; v1 = p[1];
        } else {
            v0 = make_float4(0.f, 0.f, 0.f, 0.f); v1 = v0;
        }
        const float4* q = reinterpret_cast<const float4*>(
            W + (size_t)le * ldw + off + k0 + lq);
        float4 w0 = q[0], w1 = q[1];

        __syncthreads();
        As[lq + 0][le] = v0.x; As[lq + 1][le] = v0.y;
        As[lq + 2][le] = v0.z; As[lq + 3][le] = v0.w;
        As[lq + 4][le] = v1.x; As[lq + 5][le] = v1.y;
        As[lq + 6][le] = v1.z; As[lq + 7][le] = v1.w;
        Bs[lq + 0][le] = w0.x; Bs[lq + 1][le] = w0.y;
        Bs[lq + 2][le] = w0.z; Bs[lq + 3][le] = w0.w;
        Bs[lq + 4][le] = w1.x; Bs[lq + 5][le] = w1.y;
        Bs[lq + 6][le] = w1.z; Bs[lq + 7][le] = w1.w;
        __syncthreads();

#pragma unroll
        for (int kk = 0; kk < 16; kk++) {
            float4 a0 = *reinterpret_cast<const float4*>(&As[kk][ty * 8]);
            float4 a1 = *reinterpret_cast<const float4*>(&As[kk][ty * 8 + 4]);
            ulonglong2 b01 = *reinterpret_cast<const ulonglong2*>(&Bs[kk][tx * 8]);
            ulonglong2 b23 = *reinterpret_cast<const ulonglong2*>(&Bs[kk][tx * 8 + 4]);
            unsigned long long av[8];
            av[0] = pack2(a0.x); av[1] = pack2(a0.y);
            av[2] = pack2(a0.z); av[3] = pack2(a0.w);
            av[4] = pack2(a1.x); av[5] = pack2(a1.y);
            av[6] = pack2(a1.z); av[7] = pack2(a1.w);
            unsigned long long bv[4] = {b01.x, b01.y, b23.x, b23.y};
#pragma unroll
            for (int i = 0; i < 8; i++)
#pragma unroll
                for (int j = 0; j < 4; j++)
                    ffma2(acc[i][j], av[i], bv[j]);
        }
    }
    __syncthreads();
}

// ---------------------------------------------------------------------------
// Node kernel: out = relu( Xc + agg @ W2[:,128:256].T + Un[batch] )  (fp32)
// ---------------------------------------------------------------------------
__global__ __launch_bounds__(256) void node_kernel(
    const float* __restrict__ W2, const void* __restrict__ batch,
    float* __restrict__ out, int N)
{
    __shared__ __align__(16) float As[16][132];
    __shared__ __align__(16) float Bs[16][132];

    int n0 = blockIdx.x * 128;
    unsigned long long acc[8][4];
#pragma unroll
    for (int i = 0; i < 8; i++)
#pragma unroll
        for (int j = 0; j < 4; j++) acc[i][j] = 0ull;

    tile_gemm(g_agg, n0, N, W2, 384, 128, acc, As, Bs);

    int tid = threadIdx.x;
    int tx = tid & 15, ty = tid >> 4;
    int c = tx * 8;
    int is64 = g_is64;
#pragma unroll
    for (int i = 0; i < 8; i++) {
        int row = n0 + ty * 8 + i;
        if (row < N) {
            int g = (int)ld_idx(batch, row, is64);
            const float4* pc = reinterpret_cast<const float4*>(&g_Xc[(size_t)row * 128 + c]);
            const float4* pu = reinterpret_cast<const float4*>(&g_Un[g * 128 + c]);
            float4 c0 = pc[0], c1 = pc[1];
            float4 u0 = pu[0], u1 = pu[1];
            float2 p0 = unpk(acc[i][0]), p1 = unpk(acc[i][1]);
            float2 p2 = unpk(acc[i][2]), p3 = unpk(acc[i][3]);
            float4 o0, o1;
            o0.x = fmaxf(p0.x + c0.x + u0.x, 0.f);
            o0.y = fmaxf(p0.y + c0.y + u0.y, 0.f);
            o0.z = fmaxf(p1.x + c0.z + u0.z, 0.f);
            o0.w = fmaxf(p1.y + c0.w + u0.w, 0.f);
            o1.x = fmaxf(p2.x + c1.x + u1.x, 0.f);
            o1.y = fmaxf(p2.y + c1.y + u1.y, 0.f);
            o1.z = fmaxf(p3.x + c1.z + u1.z, 0.f);
            o1.w = fmaxf(p3.y + c1.w + u1.w, 0.f);
            float4* po = reinterpret_cast<float4*>(&out[(size_t)row * 128 + c]);
            po[0] = o0; po[1] = o1;
        }
    }
}

// ---------------------------------------------------------------------------
// Launch. Inputs (metadata order): x, edge_index, edge_attr, u, batch,
//                                  W1, b1, W2, b2. Output: float [N,128].
// ---------------------------------------------------------------------------
extern "C" void kernel_launch(void* const* d_in, const int* in_sizes, int n_in,
                              void* d_out, int out_size) {
    const float* x         = (const float*)d_in[0];
    const void*  ei        = d_in[1];
    const float* edge_attr = (const float*)d_in[2];
    const float* u         = (const float*)d_in[3];
    const void*  batch     = d_in[4];
    const float* W1        = (const float*)d_in[5];
    const float* b1        = (const float*)d_in[6];
    const float* W2        = (const float*)d_in[7];
    const float* b2        = (const float*)d_in[8];
    float* out = (float*)d_out;

    int N = in_sizes[0] / FD;
    int E = in_sizes[2] / FD;
    int G = in_sizes[3] / FD;

    cudaFuncSetAttribute(edge_mma_kernel,
                         cudaFuncAttributeMaxDynamicSharedMemorySize, SM_EDGE_TOTAL);

    sniff_kernel<<<1, 1>>>((const unsigned int*)ei);

    int n4 = N * (FD / 4);
    zero_kernel<<<(n4 + 255) / 256, 256>>>(n4);

    graph_kernel<<<G, FD>>>(u, W1, b1, W2);

    dim3 pg((N + 127) / 128, 3);
    precompute_mma_kernel<<<pg, 256, SM_BSZ>>>(x, W1, W2, b2, N);

    edge_mma_kernel<<<(E + 127) / 128, 256, SM_EDGE_TOTAL>>>(edge_attr, W1, ei, batch, E);

    node_kernel<<<(N + 127) / 128, 256>>>(W2, batch, out, N);
}

// round 11
// speedup vs baseline: 1.7771x; 1.1359x over previous
#include <cuda_runtime.h>
#include <cuda_fp16.h>

// GraphNet NodeModel, algebraically factored:
//   Xau = x @ W1a.T + Ue[batch]   (fp16 table)
//   Xb  = x @ W1b.T               (fp16 table)
//   Xc  = x @ W2a.T + b2 + Un[batch]  (fp32)
//   edge_msg = relu( Xau[dst] + Xb[src] + edge_attr @ W1c.T )
//   agg      = segment_sum(edge_msg, dst)   (red.global.add.v4.f32)
//   out      = relu( Xc + agg @ W2b.T )
// Edge + precompute GEMMs: fp16 mma.sync + ldmatrix. Node GEMM: fp32 FFMA2.

#define FD 128
#define MAXN 50000
#define MAXG 64

__device__ __half g_Xau[MAXN * FD];  // x @ W1[:,0:128].T + Ue[batch]
__device__ __half g_Xb16[MAXN * FD]; // x @ W1[:,128:256].T
__device__ float  g_Xc[MAXN * FD];   // x @ W2[:,0:128].T + b2 + Un[batch]
__device__ float  g_agg[MAXN * FD];  // segment-summed edge messages
__device__ float  g_Ue[MAXG * FD];   // u @ W1[:,384:512].T + b1
__device__ float  g_Un[MAXG * FD];   // u @ W2[:,256:384].T
__device__ int    g_is64;            // 1 if indices are int64, 0 if int32

// ---------------- helpers ----------------
__device__ __forceinline__ unsigned long long pack2(float x) {
    unsigned long long r;
    asm("mov.b64 %0, {%1, %1};" : "=l"(r) : "r"(__float_as_uint(x)));
    return r;
}
__device__ __forceinline__ void ffma2(unsigned long long& d,
                                      unsigned long long a,
                                      unsigned long long b) {
    asm("fma.rn.f32x2 %0, %1, %2, %0;" : "+l"(d) : "l"(a), "l"(b));
}
__device__ __forceinline__ float2 unpk(unsigned long long v) {
    float2 f;
    asm("mov.b64 {%0, %1}, %2;" : "=f"(f.x), "=f"(f.y) : "l"(v));
    return f;
}
__device__ __forceinline__ void red_add_v4(float* p, float a, float b,
                                           float c, float d) {
    unsigned long long gp = (unsigned long long)__cvta_generic_to_global(p);
    asm volatile("red.global.add.v4.f32 [%0], {%1, %2, %3, %4};"
                 :: "l"(gp), "f"(a), "f"(b), "f"(c), "f"(d) : "memory");
}
__device__ __forceinline__ long long ld_idx(const void* p, long long i, int is64) {
    if (is64) return ((const long long*)p)[i];
    return (long long)((const int*)p)[i];
}
__device__ __forceinline__ unsigned int smem_u32(const void* p) {
    unsigned int a;
    asm("{ .reg .u64 t; cvta.to.shared.u64 t, %1; cvt.u32.u64 %0, t; }"
        : "=r"(a) : "l"(p));
    return a;
}
// float2 -> packed f16x2 (low half = .x)
__device__ __forceinline__ unsigned int f16pack(float2 f) {
    unsigned int h;
    asm("cvt.rn.f16x2.f32 %0, %1, %2;" : "=r"(h) : "f"(f.y), "f"(f.x));
    return h;
}
// m16n8k16 row.col fp16 MMA, fp32 accumulate.
__device__ __forceinline__ void mma_f16(float& c0, float& c1, float& c2, float& c3,
                                        unsigned int a0, unsigned int a1,
                                        unsigned int a2, unsigned int a3,
                                        unsigned int b0, unsigned int b1) {
    asm volatile(
        "mma.sync.aligned.m16n8k16.row.col.f32.f16.f16.f32 "
        "{%0,%1,%2,%3}, {%4,%5,%6,%7}, {%8,%9}, {%0,%1,%2,%3};"
        : "+f"(c0), "+f"(c1), "+f"(c2), "+f"(c3)
        : "r"(a0), "r"(a1), "r"(a2), "r"(a3), "r"(b0), "r"(b1));
}
__device__ __forceinline__ void ldmatrix_x4(unsigned int& r0, unsigned int& r1,
                                            unsigned int& r2, unsigned int& r3,
                                            unsigned int addr) {
    asm volatile("ldmatrix.sync.aligned.m8n8.x4.shared.b16 {%0,%1,%2,%3}, [%4];"
                 : "=r"(r0), "=r"(r1), "=r"(r2), "=r"(r3) : "r"(addr));
}

// ---------------------------------------------------------------------------
// Detect index dtype: int64 values < 2^31 have all-zero odd 32-bit words.
// ---------------------------------------------------------------------------
__global__ void sniff_kernel(const unsigned int* __restrict__ ei) {
    int is64 = 1;
#pragma unroll 1
    for (int k = 1; k < 129; k += 2) {
        if (ei[k] != 0u) { is64 = 0; break; }
    }
    g_is64 = is64;
}

__global__ void zero_kernel(int n4) {
    int i = blockIdx.x * blockDim.x + threadIdx.x;
    if (i < n4)
        reinterpret_cast<float4*>(g_agg)[i] = make_float4(0.f, 0.f, 0.f, 0.f);
}

// ---------------------------------------------------------------------------
// Per-graph GEMMs (tiny: 64 x 128 each). Block = one graph, 128 threads. fp32.
// ---------------------------------------------------------------------------
__global__ void graph_kernel(const float* __restrict__ u,
                             const float* __restrict__ W1,
                             const float* __restrict__ b1,
                             const float* __restrict__ W2) {
    __shared__ float su[FD];
    int g = blockIdx.x;
    int o = threadIdx.x;
    su[o] = u[g * FD + o];
    __syncthreads();
    float a1 = b1[o];
    float a2 = 0.f;
    const float* w1r = W1 + o * 512 + 384;
    const float* w2r = W2 + o * 384 + 256;
#pragma unroll 8
    for (int k = 0; k < FD; k++) {
        a1 = fmaf(su[k], w1r[k], a1);
        a2 = fmaf(su[k], w2r[k], a2);
    }
    g_Ue[g * FD + o] = a1;
    g_Un[g * FD + o] = a2;
}

// ---------------------------------------------------------------------------
// fp16 warp-tile GEMM pieces.
// B smem: 128 rows (out-cols) x BSTR fp16; row r holds W[r][off..off+127].
// BSTR=136 makes both ldmatrix phases and staging conflict-free.
// ---------------------------------------------------------------------------
#define BSTR 136
#define SM_B   2048                      // byte offset of B in dynamic smem
#define SM_BSZ (128 * BSTR * 2)          // 34816 bytes (fp16)
#define SM_EDGE_TOTAL (SM_B + 128 * 132 * 4)   // idx + Cbuf(aliases B): 69632

// Stage one 128x128 weight block as fp16 into smem (256 threads).
__device__ __forceinline__ void stage_B(__half* Bh, const float* __restrict__ W,
                                        int ldw, int off) {
#pragma unroll 2
    for (int g = threadIdx.x; g < 128 * 16; g += 256) {
        int r = g >> 4;
        int c0 = (g & 15) << 3;
        const float2* p = reinterpret_cast<const float2*>(W + (size_t)r * ldw + off + c0);
        unsigned int h0 = f16pack(p[0]);
        unsigned int h1 = f16pack(p[1]);
        unsigned int h2 = f16pack(p[2]);
        unsigned int h3 = f16pack(p[3]);
        *reinterpret_cast<uint4*>(Bh + r * BSTR + c0) = make_uint4(h0, h1, h2, h3);
    }
}

// Mainloop: rows r0g, r1g of fp32 A (row stride 128), B via ldmatrix.
// acc[nt][0..1] = row r0g cols nt*8+(lane&3)*2,+1 ; acc[nt][2..3] = row r1g.
__device__ __forceinline__ void mma_mainloop(
    const float* __restrict__ A, long long r0g, long long r1g, long long M,
    unsigned int sbB, int lane, float (&acc)[16][4])
{
    // per-lane ldmatrix base addresses (8 q-groups: nt pair {2q, 2q+1})
    unsigned int bbase[8];
    {
        int ii = lane & 7;
        int gg = lane >> 3;
        int nthalf = gg >> 1;     // 0 -> nt=2q, 1 -> nt=2q+1
        int khalf = gg & 1;       // +8 k columns
#pragma unroll
        for (int q = 0; q < 8; q++) {
            int row = (2 * q + nthalf) * 8 + ii;
            bbase[q] = sbB + (unsigned int)(row * (BSTR * 2)) + khalf * 16;
        }
    }

    const bool v0 = r0g < M, v1 = r1g < M;
    const float* A0 = A + r0g * 128 + (lane & 3) * 2;
    const float* A1 = A + r1g * 128 + (lane & 3) * 2;
    const float2 Z2 = make_float2(0.f, 0.f);
    float2 cur[4];
    cur[0] = v0 ? *reinterpret_cast<const float2*>(A0)     : Z2;
    cur[1] = v1 ? *reinterpret_cast<const float2*>(A1)     : Z2;
    cur[2] = v0 ? *reinterpret_cast<const float2*>(A0 + 8) : Z2;
    cur[3] = v1 ? *reinterpret_cast<const float2*>(A1 + 8) : Z2;

#pragma unroll
    for (int kc = 0; kc < 8; kc++) {
        const int k0 = kc * 16;
        float2 nxt[4];
        if (kc < 7) {
            nxt[0] = v0 ? *reinterpret_cast<const float2*>(A0 + k0 + 16) : Z2;
            nxt[1] = v1 ? *reinterpret_cast<const float2*>(A1 + k0 + 16) : Z2;
            nxt[2] = v0 ? *reinterpret_cast<const float2*>(A0 + k0 + 24) : Z2;
            nxt[3] = v1 ? *reinterpret_cast<const float2*>(A1 + k0 + 24) : Z2;
        } else {
            nxt[0] = Z2; nxt[1] = Z2; nxt[2] = Z2; nxt[3] = Z2;
        }
        unsigned int a0 = f16pack(cur[0]);
        unsigned int a1 = f16pack(cur[1]);
        unsigned int a2 = f16pack(cur[2]);
        unsigned int a3 = f16pack(cur[3]);

#pragma unroll
        for (int q = 0; q < 8; q++) {
            unsigned int b0, b1, b2, b3;
            ldmatrix_x4(b0, b1, b2, b3, bbase[q] + k0 * 2);
            mma_f16(acc[2*q][0],   acc[2*q][1],   acc[2*q][2],   acc[2*q][3],
                    a0, a1, a2, a3, b0, b1);
            mma_f16(acc[2*q+1][0], acc[2*q+1][1], acc[2*q+1][2], acc[2*q+1][3],
                    a0, a1, a2, a3, b2, b3);
        }
        cur[0] = nxt[0]; cur[1] = nxt[1]; cur[2] = nxt[2]; cur[3] = nxt[3];
    }
}

// ---------------------------------------------------------------------------
// Precompute Xau / Xb16 / Xc via fp16 mma; grid.y selects the product.
//   which 0: g_Xau = x@W1a.T + Ue[batch]   (fp16)
//   which 1: g_Xb16 = x@W1b.T              (fp16)
//   which 2: g_Xc  = x@W2a.T + b2 + Un[batch]  (fp32)
// ---------------------------------------------------------------------------
__global__ __launch_bounds__(256, 2)
void precompute_mma_kernel(const float* __restrict__ x,
                           const float* __restrict__ W1,
                           const float* __restrict__ W2,
                           const float* __restrict__ b2,
                           const void* __restrict__ batch, int N)
{
    extern __shared__ __align__(16) char smem[];
    __half* Bh = (__half*)smem;

    const float* W; int ldw, off;
    int which = blockIdx.y;
    if (which == 0)      { W = W1; ldw = 512; off = 0;   }
    else if (which == 1) { W = W1; ldw = 512; off = 128; }
    else                 { W = W2; ldw = 384; off = 0;   }

    stage_B(Bh, W, ldw, off);
    __syncthreads();

    const int tid = threadIdx.x;
    const int wid = tid >> 5;
    const int lane = tid & 31;
    const long long m0 = (long long)blockIdx.x * 128;
    const long long r0 = m0 + wid * 16 + (lane >> 2);
    const long long r1 = r0 + 8;

    float acc[16][4];
#pragma unroll
    for (int t = 0; t < 16; t++)
#pragma unroll
        for (int j = 0; j < 4; j++) acc[t][j] = 0.f;

    mma_mainloop(x, r0, r1, N, smem_u32(Bh), lane, acc);

    const int cb = (lane & 3) * 2;
    const int is64 = g_is64;
#pragma unroll
    for (int h = 0; h < 2; h++) {
        long long row = h ? r1 : r0;
        if (row >= N) continue;
        const float* uadd = 0;
        if (which == 0)
            uadd = g_Ue + (size_t)ld_idx(batch, row, is64) * 128;
        else if (which == 2)
            uadd = g_Un + (size_t)ld_idx(batch, row, is64) * 128;
#pragma unroll
        for (int nt = 0; nt < 16; nt++) {
            int c = nt * 8 + cb;
            float vx = acc[nt][2 * h], vy = acc[nt][2 * h + 1];
            if (uadd) { vx += uadd[c]; vy += uadd[c + 1]; }
            if (which == 2) {
                vx += b2[c]; vy += b2[c + 1];
                *reinterpret_cast<float2*>(g_Xc + row * 128 + c) = make_float2(vx, vy);
            } else {
                __half2 hv = __floats2half2_rn(vx, vy);
                __half* T = (which == 0) ? g_Xau : g_Xb16;
                *reinterpret_cast<__half2*>(T + row * 128 + c) = hv;
            }
        }
    }
}

// ---------------------------------------------------------------------------
// Edge kernel: Ea = edge_attr @ W1c.T via fp16 mma; C staged through smem
// (aliases B); epilogue gathers fp16 Xau[dst] + Xb[src], relu, red.v4.
// 128 edges per block, 8 warps.
// ---------------------------------------------------------------------------
__global__ __launch_bounds__(256, 2)
void edge_mma_kernel(const float* __restrict__ edge_attr,
                     const float* __restrict__ W1,
                     const void* __restrict__ ei, int E)
{
    extern __shared__ __align__(16) char smem[];
    int* sDst = (int*)smem;
    int* sSrc = sDst + 128;
    __half* Bh = (__half*)(smem + SM_B);
    float* Cbuf = (float*)(smem + SM_B);          // [128][132], aliases B

    const int tid = threadIdx.x;
    const int wid = tid >> 5;
    const int lane = tid & 31;
    const long long e0 = (long long)blockIdx.x * 128;

    // indices
    if (tid < 128) {
        int is64 = g_is64;
        long long ge = e0 + tid;
        if (ge < E) {
            sSrc[tid] = (int)ld_idx(ei, ge, is64);
            sDst[tid] = (int)ld_idx(ei, (long long)E + ge, is64);
        } else {
            sSrc[tid] = 0; sDst[tid] = 0;
        }
    }

    stage_B(Bh, W1, 512, 256);   // W1c = W1[:,256:384]
    __syncthreads();

    const long long r0 = e0 + wid * 16 + (lane >> 2);
    const long long r1 = r0 + 8;

    float acc[16][4];
#pragma unroll
    for (int t = 0; t < 16; t++)
#pragma unroll
        for (int j = 0; j < 4; j++) acc[t][j] = 0.f;

    mma_mainloop(edge_attr, r0, r1, E, smem_u32(Bh), lane, acc);

    // ---- stage C to smem (B no longer needed) ----
    __syncthreads();
    {
        const int rbase = wid * 16 + (lane >> 2);
        const int cb = (lane & 3) * 2;
#pragma unroll
        for (int nt = 0; nt < 16; nt++) {
            float* p0 = Cbuf + rbase * 132 + nt * 8 + cb;
            *reinterpret_cast<float2*>(p0)           = make_float2(acc[nt][0], acc[nt][1]);
            *reinterpret_cast<float2*>(p0 + 8 * 132) = make_float2(acc[nt][2], acc[nt][3]);
        }
    }
    __syncthreads();

    // ---- epilogue: fp16 gathers + relu + scatter-add (2 threads per edge) ----
    {
        const int el = tid >> 1;
        const int cb = (tid & 1) * 64;
        if (e0 + el < E) {
            int d = sDst[el], s = sSrc[el];
            const __half* xa = g_Xau + (size_t)d * 128 + cb;
            const __half* xb = g_Xb16 + (size_t)s * 128 + cb;
            float* dp = g_agg + (size_t)d * 128 + cb;
            const float* cr = Cbuf + el * 132 + cb;
#pragma unroll
            for (int j = 0; j < 16; j++) {
                int c = j * 4;
                float4 m  = *reinterpret_cast<const float4*>(cr + c);
                uint2 ua = *reinterpret_cast<const uint2*>(xa + c);
                uint2 ub = *reinterpret_cast<const uint2*>(xb + c);
                float2 a0 = __half22float2(*reinterpret_cast<__half2*>(&ua.x));
                float2 a1 = __half22float2(*reinterpret_cast<__half2*>(&ua.y));
                float2 b0 = __half22float2(*reinterpret_cast<__half2*>(&ub.x));
                float2 b1 = __half22float2(*reinterpret_cast<__half2*>(&ub.y));
                float w0 = fmaxf(m.x + a0.x + b0.x, 0.f);
                float w1 = fmaxf(m.y + a0.y + b0.y, 0.f);
                float w2 = fmaxf(m.z + a1.x + b1.x, 0.f);
                float w3 = fmaxf(m.w + a1.y + b1.y, 0.f);
                red_add_v4(dp + c, w0, w1, w2, w3);
            }
        }
    }
}

// ---------------------------------------------------------------------------
// FFMA2 tile GEMM (node kernel): 128x128xK=128, 256 threads. fp32 exact.
// ---------------------------------------------------------------------------
__device__ __forceinline__ void tile_gemm(
    const float* __restrict__ A, int rowBase, int M,
    const float* __restrict__ W, int ldw, int off,
    unsigned long long (&acc)[8][4], float (*As)[132], float (*Bs)[132])
{
    const int tid = threadIdx.x;
    const int le = tid & 127;
    const int lq = (tid >> 7) << 3;
    const int tx = tid & 15;
    const int ty = tid >> 4;

#pragma unroll 1
    for (int k0 = 0; k0 < 128; k0 += 16) {
        float4 v0, v1;
        int row = rowBase + le;
        if (row < M) {
            const float4* p = reinterpret_cast<const float4*>(
                A + (size_t)row * 128 + k0 + lq);
            v0 = p[0]; v1 = p[1];
        } else {
            v0 = make_float4(0.f, 0.f, 0.f, 0.f); v1 = v0;
        }
        const float4* q = reinterpret_cast<const float4*>(
            W + (size_t)le * ldw + off + k0 + lq);
        float4 w0 = q[0], w1 = q[1];

        __syncthreads();
        As[lq + 0][le] = v0.x; As[lq + 1][le] = v0.y;
        As[lq + 2][le] = v0.z; As[lq + 3][le] = v0.w;
        As[lq + 4][le] = v1.x; As[lq + 5][le] = v1.y;
        As[lq + 6][le] = v1.z; As[lq + 7][le] = v1.w;
        Bs[lq + 0][le] = w0.x; Bs[lq + 1][le] = w0.y;
        Bs[lq + 2][le] = w0.z; Bs[lq + 3][le] = w0.w;
        Bs[lq + 4][le] = w1.x; Bs[lq + 5][le] = w1.y;
        Bs[lq + 6][le] = w1.z; Bs[lq + 7][le] = w1.w;
        __syncthreads();

#pragma unroll
        for (int kk = 0; kk < 16; kk++) {
            float4 a0 = *reinterpret_cast<const float4*>(&As[kk][ty * 8]);
            float4 a1 = *reinterpret_cast<const float4*>(&As[kk][ty * 8 + 4]);
            ulonglong2 b01 = *reinterpret_cast<const ulonglong2*>(&Bs[kk][tx * 8]);
            ulonglong2 b23 = *reinterpret_cast<const ulonglong2*>(&Bs[kk][tx * 8 + 4]);
            unsigned long long av[8];
            av[0] = pack2(a0.x); av[1] = pack2(a0.y);
            av[2] = pack2(a0.z); av[3] = pack2(a0.w);
            av[4] = pack2(a1.x); av[5] = pack2(a1.y);
            av[6] = pack2(a1.z); av[7] = pack2(a1.w);
            unsigned long long bv[4] = {b01.x, b01.y, b23.x, b23.y};
#pragma unroll
            for (int i = 0; i < 8; i++)
#pragma unroll
                for (int j = 0; j < 4; j++)
                    ffma2(acc[i][j], av[i], bv[j]);
        }
    }
    __syncthreads();
}

// ---------------------------------------------------------------------------
// Node kernel: out = relu( Xc + agg @ W2[:,128:256].T )  (fp32; Un folded in Xc)
// ---------------------------------------------------------------------------
__global__ __launch_bounds__(256) void node_kernel(
    const float* __restrict__ W2, float* __restrict__ out, int N)
{
    __shared__ __align__(16) float As[16][132];
    __shared__ __align__(16) float Bs[16][132];

    int n0 = blockIdx.x * 128;
    unsigned long long acc[8][4];
#pragma unroll
    for (int i = 0; i < 8; i++)
#pragma unroll
        for (int j = 0; j < 4; j++) acc[i][j] = 0ull;

    tile_gemm(g_agg, n0, N, W2, 384, 128, acc, As, Bs);

    int tid = threadIdx.x;
    int tx = tid & 15, ty = tid >> 4;
    int c = tx * 8;
#pragma unroll
    for (int i = 0; i < 8; i++) {
        int row = n0 + ty * 8 + i;
        if (row < N) {
            const float4* pc = reinterpret_cast<const float4*>(&g_Xc[(size_t)row * 128 + c]);
            float4 c0 = pc[0], c1 = pc[1];
            float2 p0 = unpk(acc[i][0]), p1 = unpk(acc[i][1]);
            float2 p2 = unpk(acc[i][2]), p3 = unpk(acc[i][3]);
            float4 o0, o1;
            o0.x = fmaxf(p0.x + c0.x, 0.f);
            o0.y = fmaxf(p0.y + c0.y, 0.f);
            o0.z = fmaxf(p1.x + c0.z, 0.f);
            o0.w = fmaxf(p1.y + c0.w, 0.f);
            o1.x = fmaxf(p2.x + c1.x, 0.f);
            o1.y = fmaxf(p2.y + c1.y, 0.f);
            o1.z = fmaxf(p3.x + c1.z, 0.f);
            o1.w = fmaxf(p3.y + c1.w, 0.f);
            float4* po = reinterpret_cast<float4*>(&out[(size_t)row * 128 + c]);
            po[0] = o0; po[1] = o1;
        }
    }
}

// ---------------------------------------------------------------------------
// Launch. Inputs (metadata order): x, edge_index, edge_attr, u, batch,
//                                  W1, b1, W2, b2. Output: float [N,128].
// ---------------------------------------------------------------------------
extern "C" void kernel_launch(void* const* d_in, const int* in_sizes, int n_in,
                              void* d_out, int out_size) {
    const float* x         = (const float*)d_in[0];
    const void*  ei        = d_in[1];
    const float* edge_attr = (const float*)d_in[2];
    const float* u         = (const float*)d_in[3];
    const void*  batch     = d_in[4];
    const float* W1        = (const float*)d_in[5];
    const float* b1        = (const float*)d_in[6];
    const float* W2        = (const float*)d_in[7];
    const float* b2        = (const float*)d_in[8];
    float* out = (float*)d_out;

    int N = in_sizes[0] / FD;
    int E = in_sizes[2] / FD;
    int G = in_sizes[3] / FD;

    cudaFuncSetAttribute(edge_mma_kernel,
                         cudaFuncAttributeMaxDynamicSharedMemorySize, SM_EDGE_TOTAL);

    sniff_kernel<<<1, 1>>>((const unsigned int*)ei);

    int n4 = N * (FD / 4);
    zero_kernel<<<(n4 + 255) / 256, 256>>>(n4);

    graph_kernel<<<G, FD>>>(u, W1, b1, W2);

    dim3 pg((N + 127) / 128, 3);
    precompute_mma_kernel<<<pg, 256, SM_BSZ>>>(x, W1, W2, b2, batch, N);

    edge_mma_kernel<<<(E + 127) / 128, 256, SM_EDGE_TOTAL>>>(edge_attr, W1, ei, E);

    node_kernel<<<(N + 127) / 128, 256>>>(W2, out, N);
}

// round 12
// speedup vs baseline: 2.2057x; 1.2412x over previous
#include <cuda_runtime.h>
#include <cuda_fp16.h>

// GraphNet NodeModel, algebraically factored:
//   Xau = x @ W1a.T + Ue[batch]   (fp16 table)
//   Xb  = x @ W1b.T               (fp16 table)
//   Xc  = x @ W2a.T + b2 + Un[batch]  (fp32)
//   edge_msg = relu( Xau[dst] + Xb[src] + edge_attr @ W1c.T )
//   agg      = segment_sum(edge_msg, dst)   (red.global.add.v4.f32)
//   out      = relu( Xc + agg @ W2b.T )
// Edge + precompute GEMMs: fp16 mma.sync, BOTH operands staged to smem and
// fed via ldmatrix (dense compute phase, high-MLP staging phase).
// Node GEMM: fp32 FFMA2.

#define FD 128
#define MAXN 50000
#define MAXG 64

__device__ __half g_Xau[MAXN * FD];  // x @ W1[:,0:128].T + Ue[batch]
__device__ __half g_Xb16[MAXN * FD]; // x @ W1[:,128:256].T
__device__ float  g_Xc[MAXN * FD];   // x @ W2[:,0:128].T + b2 + Un[batch]
__device__ float  g_agg[MAXN * FD];  // segment-summed edge messages
__device__ float  g_Ue[MAXG * FD];   // u @ W1[:,384:512].T + b1
__device__ float  g_Un[MAXG * FD];   // u @ W2[:,256:384].T
__device__ int    g_is64;            // 1 if indices are int64, 0 if int32

// ---------------- helpers ----------------
__device__ __forceinline__ unsigned long long pack2(float x) {
    unsigned long long r;
    asm("mov.b64 %0, {%1, %1};" : "=l"(r) : "r"(__float_as_uint(x)));
    return r;
}
__device__ __forceinline__ void ffma2(unsigned long long& d,
                                      unsigned long long a,
                                      unsigned long long b) {
    asm("fma.rn.f32x2 %0, %1, %2, %0;" : "+l"(d) : "l"(a), "l"(b));
}
__device__ __forceinline__ float2 unpk(unsigned long long v) {
    float2 f;
    asm("mov.b64 {%0, %1}, %2;" : "=f"(f.x), "=f"(f.y) : "l"(v));
    return f;
}
__device__ __forceinline__ void red_add_v4(float* p, float a, float b,
                                           float c, float d) {
    unsigned long long gp = (unsigned long long)__cvta_generic_to_global(p);
    asm volatile("red.global.add.v4.f32 [%0], {%1, %2, %3, %4};"
                 :: "l"(gp), "f"(a), "f"(b), "f"(c), "f"(d) : "memory");
}
__device__ __forceinline__ long long ld_idx(const void* p, long long i, int is64) {
    if (is64) return ((const long long*)p)[i];
    return (long long)((const int*)p)[i];
}
__device__ __forceinline__ unsigned int smem_u32(const void* p) {
    unsigned int a;
    asm("{ .reg .u64 t; cvta.to.shared.u64 t, %1; cvt.u32.u64 %0, t; }"
        : "=r"(a) : "l"(p));
    return a;
}
// float2 -> packed f16x2 (low half = .x)
__device__ __forceinline__ unsigned int f16pack(float2 f) {
    unsigned int h;
    asm("cvt.rn.f16x2.f32 %0, %1, %2;" : "=r"(h) : "f"(f.y), "f"(f.x));
    return h;
}
// m16n8k16 row.col fp16 MMA, fp32 accumulate.
__device__ __forceinline__ void mma_f16(float& c0, float& c1, float& c2, float& c3,
                                        unsigned int a0, unsigned int a1,
                                        unsigned int a2, unsigned int a3,
                                        unsigned int b0, unsigned int b1) {
    asm volatile(
        "mma.sync.aligned.m16n8k16.row.col.f32.f16.f16.f32 "
        "{%0,%1,%2,%3}, {%4,%5,%6,%7}, {%8,%9}, {%0,%1,%2,%3};"
        : "+f"(c0), "+f"(c1), "+f"(c2), "+f"(c3)
        : "r"(a0), "r"(a1), "r"(a2), "r"(a3), "r"(b0), "r"(b1));
}
__device__ __forceinline__ void ldmatrix_x4(unsigned int& r0, unsigned int& r1,
                                            unsigned int& r2, unsigned int& r3,
                                            unsigned int addr) {
    asm volatile("ldmatrix.sync.aligned.m8n8.x4.shared.b16 {%0,%1,%2,%3}, [%4];"
                 : "=r"(r0), "=r"(r1), "=r"(r2), "=r"(r3) : "r"(addr));
}

// ---------------------------------------------------------------------------
// Detect index dtype: int64 values < 2^31 have all-zero odd 32-bit words.
// ---------------------------------------------------------------------------
__global__ void sniff_kernel(const unsigned int* __restrict__ ei) {
    int is64 = 1;
#pragma unroll 1
    for (int k = 1; k < 129; k += 2) {
        if (ei[k] != 0u) { is64 = 0; break; }
    }
    g_is64 = is64;
}

__global__ void zero_kernel(int n4) {
    int i = blockIdx.x * blockDim.x + threadIdx.x;
    if (i < n4)
        reinterpret_cast<float4*>(g_agg)[i] = make_float4(0.f, 0.f, 0.f, 0.f);
}

// ---------------------------------------------------------------------------
// Per-graph GEMMs (tiny: 64 x 128 each). Block = one graph, 128 threads. fp32.
// ---------------------------------------------------------------------------
__global__ void graph_kernel(const float* __restrict__ u,
                             const float* __restrict__ W1,
                             const float* __restrict__ b1,
                             const float* __restrict__ W2) {
    __shared__ float su[FD];
    int g = blockIdx.x;
    int o = threadIdx.x;
    su[o] = u[g * FD + o];
    __syncthreads();
    float a1 = b1[o];
    float a2 = 0.f;
    const float* w1r = W1 + o * 512 + 384;
    const float* w2r = W2 + o * 384 + 256;
#pragma unroll 8
    for (int k = 0; k < FD; k++) {
        a1 = fmaf(su[k], w1r[k], a1);
        a2 = fmaf(su[k], w2r[k], a2);
    }
    g_Ue[g * FD + o] = a1;
    g_Un[g * FD + o] = a2;
}

// ---------------------------------------------------------------------------
// fp16 warp-tile GEMM pieces. Both operands staged to smem (stride BSTR fp16).
// ---------------------------------------------------------------------------
#define BSTR 136
#define TILE_BYTES (128 * BSTR * 2)      // 34816 bytes per staged 128x128 tile
#define SM_B   2048
#define SM_A   (SM_B + TILE_BYTES)       // 36864
#define SM_EDGE_TOTAL (SM_A + TILE_BYTES)      // 71680
#define SM_PRE_TOTAL  (2 * TILE_BYTES + 64)    // 69696

// Stage a 128x128 fp32 block (row stride ldsrc, col offset off, row base
// rowBase, guarded by M) into fp16 smem. 256 threads, fully unrolled (MLP 16).
__device__ __forceinline__ void stage_fp16(__half* S, const float* __restrict__ src,
                                           long long rowBase, long long M,
                                           int ldsrc, int off) {
#pragma unroll
    for (int it = 0; it < 8; it++) {
        int g = threadIdx.x + it * 256;
        int r = g >> 4;
        int c0 = (g & 15) << 3;
        uint4 out;
        long long row = rowBase + r;
        if (row < M) {
            const float4* p = reinterpret_cast<const float4*>(
                src + row * ldsrc + off + c0);
            float4 f0 = p[0], f1 = p[1];
            out = make_uint4(f16pack(make_float2(f0.x, f0.y)),
                             f16pack(make_float2(f0.z, f0.w)),
                             f16pack(make_float2(f1.x, f1.y)),
                             f16pack(make_float2(f1.z, f1.w)));
        } else {
            out = make_uint4(0u, 0u, 0u, 0u);
        }
        *reinterpret_cast<uint4*>(S + r * BSTR + c0) = out;
    }
}

// Dense smem-smem mainloop: A-frags and B-frags via ldmatrix.x4.
// acc[nt][0..1] = row (wid*16 + lane/4), cols nt*8+(lane&3)*2,+1;
// acc[nt][2..3] = row +8.
__device__ __forceinline__ void mma_mainloop_sm(
    unsigned int sbA, unsigned int sbB, int wid, int lane, float (&acc)[16][4])
{
    // A-frag addresses: lanes 0-15 -> rows 0..15 (k 0-7), lanes 16-31 -> +16B
    unsigned int abase = sbA
        + (unsigned int)((wid * 16 + (lane & 15)) * (BSTR * 2))
        + (unsigned int)((lane >> 4) * 16);

    unsigned int bbase[8];
    {
        int ii = lane & 7;
        int gg = lane >> 3;
        int nthalf = gg >> 1;
        int khalf = gg & 1;
#pragma unroll
        for (int q = 0; q < 8; q++) {
            int row = (2 * q + nthalf) * 8 + ii;
            bbase[q] = sbB + (unsigned int)(row * (BSTR * 2)) + khalf * 16;
        }
    }

#pragma unroll
    for (int kc = 0; kc < 8; kc++) {
        const int koff = kc * 32;   // 16 fp16 = 32 bytes per kc
        unsigned int a0, a1, a2, a3;
        ldmatrix_x4(a0, a1, a2, a3, abase + koff);
#pragma unroll
        for (int q = 0; q < 8; q++) {
            unsigned int b0, b1, b2, b3;
            ldmatrix_x4(b0, b1, b2, b3, bbase[q] + koff);
            mma_f16(acc[2*q][0],   acc[2*q][1],   acc[2*q][2],   acc[2*q][3],
                    a0, a1, a2, a3, b0, b1);
            mma_f16(acc[2*q+1][0], acc[2*q+1][1], acc[2*q+1][2], acc[2*q+1][3],
                    a0, a1, a2, a3, b2, b3);
        }
    }
}

// ---------------------------------------------------------------------------
// Precompute Xau / Xb16 / Xc via fp16 mma; grid.y selects the product.
//   which 0: g_Xau = x@W1a.T + Ue[batch]   (fp16)
//   which 1: g_Xb16 = x@W1b.T              (fp16)
//   which 2: g_Xc  = x@W2a.T + b2 + Un[batch]  (fp32)
// ---------------------------------------------------------------------------
__global__ __launch_bounds__(256, 2)
void precompute_mma_kernel(const float* __restrict__ x,
                           const float* __restrict__ W1,
                           const float* __restrict__ W2,
                           const float* __restrict__ b2,
                           const void* __restrict__ batch, int N)
{
    extern __shared__ __align__(16) char smem[];
    __half* Bh = (__half*)smem;
    __half* Ah = (__half*)(smem + TILE_BYTES);

    const float* W; int ldw, off;
    int which = blockIdx.y;
    if (which == 0)      { W = W1; ldw = 512; off = 0;   }
    else if (which == 1) { W = W1; ldw = 512; off = 128; }
    else                 { W = W2; ldw = 384; off = 0;   }

    const long long m0 = (long long)blockIdx.x * 128;
    stage_fp16(Bh, W, 0, 128, ldw, off);
    stage_fp16(Ah, x, m0, N, 128, 0);
    __syncthreads();

    const int tid = threadIdx.x;
    const int wid = tid >> 5;
    const int lane = tid & 31;
    const long long r0 = m0 + wid * 16 + (lane >> 2);
    const long long r1 = r0 + 8;

    float acc[16][4];
#pragma unroll
    for (int t = 0; t < 16; t++)
#pragma unroll
        for (int j = 0; j < 4; j++) acc[t][j] = 0.f;

    mma_mainloop_sm(smem_u32(Ah), smem_u32(Bh), wid, lane, acc);

    const int cb = (lane & 3) * 2;
    const int is64 = g_is64;
#pragma unroll
    for (int h = 0; h < 2; h++) {
        long long row = h ? r1 : r0;
        if (row >= N) continue;
        const float* uadd = 0;
        if (which == 0)
            uadd = g_Ue + (size_t)ld_idx(batch, row, is64) * 128;
        else if (which == 2)
            uadd = g_Un + (size_t)ld_idx(batch, row, is64) * 128;
#pragma unroll
        for (int nt = 0; nt < 16; nt++) {
            int c = nt * 8 + cb;
            float vx = acc[nt][2 * h], vy = acc[nt][2 * h + 1];
            if (uadd) { vx += uadd[c]; vy += uadd[c + 1]; }
            if (which == 2) {
                vx += b2[c]; vy += b2[c + 1];
                *reinterpret_cast<float2*>(g_Xc + row * 128 + c) = make_float2(vx, vy);
            } else {
                __half2 hv = __floats2half2_rn(vx, vy);
                __half* T = (which == 0) ? g_Xau : g_Xb16;
                *reinterpret_cast<__half2*>(T + row * 128 + c) = hv;
            }
        }
    }
}

// ---------------------------------------------------------------------------
// Edge kernel: Ea = edge_attr @ W1c.T via fp16 mma (A+B staged); C staged
// through smem (aliases A/B); epilogue gathers fp16 Xau[dst] + Xb[src],
// relu, red.global.add.v4. 128 edges per block, 8 warps.
// ---------------------------------------------------------------------------
__global__ __launch_bounds__(256, 2)
void edge_mma_kernel(const float* __restrict__ edge_attr,
                     const float* __restrict__ W1,
                     const void* __restrict__ ei, int E)
{
    extern __shared__ __align__(16) char smem[];
    int* sDst = (int*)smem;
    int* sSrc = sDst + 128;
    __half* Bh = (__half*)(smem + SM_B);
    __half* Ah = (__half*)(smem + SM_A);
    float* Cbuf = (float*)(smem + SM_B);   // [128][132] = 67584 B, aliases A+B

    const int tid = threadIdx.x;
    const int wid = tid >> 5;
    const int lane = tid & 31;
    const long long e0 = (long long)blockIdx.x * 128;

    // indices
    if (tid < 128) {
        int is64 = g_is64;
        long long ge = e0 + tid;
        if (ge < E) {
            sSrc[tid] = (int)ld_idx(ei, ge, is64);
            sDst[tid] = (int)ld_idx(ei, (long long)E + ge, is64);
        } else {
            sSrc[tid] = 0; sDst[tid] = 0;
        }
    }

    stage_fp16(Bh, W1, 0, 128, 512, 256);     // W1c = W1[:,256:384]
    stage_fp16(Ah, edge_attr, e0, E, 128, 0);
    __syncthreads();

    float acc[16][4];
#pragma unroll
    for (int t = 0; t < 16; t++)
#pragma unroll
        for (int j = 0; j < 4; j++) acc[t][j] = 0.f;

    mma_mainloop_sm(smem_u32(Ah), smem_u32(Bh), wid, lane, acc);

    // ---- stage C to smem (A/B no longer needed) ----
    __syncthreads();
    {
        const int rbase = wid * 16 + (lane >> 2);
        const int cb = (lane & 3) * 2;
#pragma unroll
        for (int nt = 0; nt < 16; nt++) {
            float* p0 = Cbuf + rbase * 132 + nt * 8 + cb;
            *reinterpret_cast<float2*>(p0)           = make_float2(acc[nt][0], acc[nt][1]);
            *reinterpret_cast<float2*>(p0 + 8 * 132) = make_float2(acc[nt][2], acc[nt][3]);
        }
    }
    __syncthreads();

    // ---- epilogue: fp16 uint4 gathers + relu + red.v4 (2 threads/edge) ----
    {
        const int el = tid >> 1;
        const int cb = (tid & 1) * 64;
        if (e0 + el < E) {
            int d = sDst[el], s = sSrc[el];
            const __half* xa = g_Xau + (size_t)d * 128 + cb;
            const __half* xb = g_Xb16 + (size_t)s * 128 + cb;
            float* dp = g_agg + (size_t)d * 128 + cb;
            const float* cr = Cbuf + el * 132 + cb;
#pragma unroll
            for (int j = 0; j < 8; j++) {
                int c = j * 8;
                float4 m0 = *reinterpret_cast<const float4*>(cr + c);
                float4 m1 = *reinterpret_cast<const float4*>(cr + c + 4);
                uint4 ua = *reinterpret_cast<const uint4*>(xa + c);
                uint4 ub = *reinterpret_cast<const uint4*>(xb + c);
                float2 a0 = __half22float2(*reinterpret_cast<__half2*>(&ua.x));
                float2 a1 = __half22float2(*reinterpret_cast<__half2*>(&ua.y));
                float2 a2 = __half22float2(*reinterpret_cast<__half2*>(&ua.z));
                float2 a3 = __half22float2(*reinterpret_cast<__half2*>(&ua.w));
                float2 b0 = __half22float2(*reinterpret_cast<__half2*>(&ub.x));
                float2 b1 = __half22float2(*reinterpret_cast<__half2*>(&ub.y));
                float2 b2 = __half22float2(*reinterpret_cast<__half2*>(&ub.z));
                float2 b3 = __half22float2(*reinterpret_cast<__half2*>(&ub.w));
                float w0 = fmaxf(m0.x + a0.x + b0.x, 0.f);
                float w1 = fmaxf(m0.y + a0.y + b0.y, 0.f);
                float w2 = fmaxf(m0.z + a1.x + b1.x, 0.f);
                float w3 = fmaxf(m0.w + a1.y + b1.y, 0.f);
                red_add_v4(dp + c, w0, w1, w2, w3);
                float w4 = fmaxf(m1.x + a2.x + b2.x, 0.f);
                float w5 = fmaxf(m1.y + a2.y + b2.y, 0.f);
                float w6 = fmaxf(m1.z + a3.x + b3.x, 0.f);
                float w7 = fmaxf(m1.w + a3.y + b3.y, 0.f);
                red_add_v4(dp + c + 4, w4, w5, w6, w7);
            }
        }
    }
}

// ---------------------------------------------------------------------------
// FFMA2 tile GEMM (node kernel): 128x128xK=128, 256 threads. fp32 exact.
// ---------------------------------------------------------------------------
__device__ __forceinline__ void tile_gemm(
    const float* __restrict__ A, int rowBase, int M,
    const float* __restrict__ W, int ldw, int off,
    unsigned long long (&acc)[8][4], float (*As)[132], float (*Bs)[132])
{
    const int tid = threadIdx.x;
    const int le = tid & 127;
    const int lq = (tid >> 7) << 3;
    const int tx = tid & 15;
    const int ty = tid >> 4;

#pragma unroll 1
    for (int k0 = 0; k0 < 128; k0 += 16) {
        float4 v0, v1;
        int row = rowBase + le;
        if (row < M) {
            const float4* p = reinterpret_cast<const float4*>(
                A + (size_t)row * 128 + k0 + lq);
            v0 = p[0]; v1 = p[1];
        } else {
            v0 = make_float4(0.f, 0.f, 0.f, 0.f); v1 = v0;
        }
        const float4* q = reinterpret_cast<const float4*>(
            W + (size_t)le * ldw + off + k0 + lq);
        float4 w0 = q[0], w1 = q[1];

        __syncthreads();
        As[lq + 0][le] = v0.x; As[lq + 1][le] = v0.y;
        As[lq + 2][le] = v0.z; As[lq + 3][le] = v0.w;
        As[lq + 4][le] = v1.x; As[lq + 5][le] = v1.y;
        As[lq + 6][le] = v1.z; As[lq + 7][le] = v1.w;
        Bs[lq + 0][le] = w0.x; Bs[lq + 1][le] = w0.y;
        Bs[lq + 2][le] = w0.z; Bs[lq + 3][le] = w0.w;
        Bs[lq + 4][le] = w1.x; Bs[lq + 5][le] = w1.y;
        Bs[lq + 6][le] = w1.z; Bs[lq + 7][le] = w1.w;
        __syncthreads();

#pragma unroll
        for (int kk = 0; kk < 16; kk++) {
            float4 a0 = *reinterpret_cast<const float4*>(&As[kk][ty * 8]);
            float4 a1 = *reinterpret_cast<const float4*>(&As[kk][ty * 8 + 4]);
            ulonglong2 b01 = *reinterpret_cast<const ulonglong2*>(&Bs[kk][tx * 8]);
            ulonglong2 b23 = *reinterpret_cast<const ulonglong2*>(&Bs[kk][tx * 8 + 4]);
            unsigned long long av[8];
            av[0] = pack2(a0.x); av[1] = pack2(a0.y);
            av[2] = pack2(a0.z); av[3] = pack2(a0.w);
            av[4] = pack2(a1.x); av[5] = pack2(a1.y);
            av[6] = pack2(a1.z); av[7] = pack2(a1.w);
            unsigned long long bv[4] = {b01.x, b01.y, b23.x, b23.y};
#pragma unroll
            for (int i = 0; i < 8; i++)
#pragma unroll
                for (int j = 0; j < 4; j++)
                    ffma2(acc[i][j], av[i], bv[j]);
        }
    }
    __syncthreads();
}

// ---------------------------------------------------------------------------
// Node kernel: out = relu( Xc + agg @ W2[:,128:256].T )  (fp32; Un folded in Xc)
// ---------------------------------------------------------------------------
__global__ __launch_bounds__(256) void node_kernel(
    const float* __restrict__ W2, float* __restrict__ out, int N)
{
    __shared__ __align__(16) float As[16][132];
    __shared__ __align__(16) float Bs[16][132];

    int n0 = blockIdx.x * 128;
    unsigned long long acc[8][4];
#pragma unroll
    for (int i = 0; i < 8; i++)
#pragma unroll
        for (int j = 0; j < 4; j++) acc[i][j] = 0ull;

    tile_gemm(g_agg, n0, N, W2, 384, 128, acc, As, Bs);

    int tid = threadIdx.x;
    int tx = tid & 15, ty = tid >> 4;
    int c = tx * 8;
#pragma unroll
    for (int i = 0; i < 8; i++) {
        int row = n0 + ty * 8 + i;
        if (row < N) {
            const float4* pc = reinterpret_cast<const float4*>(&g_Xc[(size_t)row * 128 + c]);
            float4 c0 = pc[0], c1 = pc[1];
            float2 p0 = unpk(acc[i][0]), p1 = unpk(acc[i][1]);
            float2 p2 = unpk(acc[i][2]), p3 = unpk(acc[i][3]);
            float4 o0, o1;
            o0.x = fmaxf(p0.x + c0.x, 0.f);
            o0.y = fmaxf(p0.y + c0.y, 0.f);
            o0.z = fmaxf(p1.x + c0.z, 0.f);
            o0.w = fmaxf(p1.y + c0.w, 0.f);
            o1.x = fmaxf(p2.x + c1.x, 0.f);
            o1.y = fmaxf(p2.y + c1.y, 0.f);
            o1.z = fmaxf(p3.x + c1.z, 0.f);
            o1.w = fmaxf(p3.y + c1.w, 0.f);
            float4* po = reinterpret_cast<float4*>(&out[(size_t)row * 128 + c]);
            po[0] = o0; po[1] = o1;
        }
    }
}

// ---------------------------------------------------------------------------
// Launch. Inputs (metadata order): x, edge_index, edge_attr, u, batch,
//                                  W1, b1, W2, b2. Output: float [N,128].
// ---------------------------------------------------------------------------
extern "C" void kernel_launch(void* const* d_in, const int* in_sizes, int n_in,
                              void* d_out, int out_size) {
    const float* x         = (const float*)d_in[0];
    const void*  ei        = d_in[1];
    const float* edge_attr = (const float*)d_in[2];
    const float* u         = (const float*)d_in[3];
    const void*  batch     = d_in[4];
    const float* W1        = (const float*)d_in[5];
    const float* b1        = (const float*)d_in[6];
    const float* W2        = (const float*)d_in[7];
    const float* b2        = (const float*)d_in[8];
    float* out = (float*)d_out;

    int N = in_sizes[0] / FD;
    int E = in_sizes[2] / FD;
    int G = in_sizes[3] / FD;

    cudaFuncSetAttribute(edge_mma_kernel,
                         cudaFuncAttributeMaxDynamicSharedMemorySize, SM_EDGE_TOTAL);
    cudaFuncSetAttribute(precompute_mma_kernel,
                         cudaFuncAttributeMaxDynamicSharedMemorySize, SM_PRE_TOTAL);

    sniff_kernel<<<1, 1>>>((const unsigned int*)ei);

    int n4 = N * (FD / 4);
    zero_kernel<<<(n4 + 255) / 256, 256>>>(n4);

    graph_kernel<<<G, FD>>>(u, W1, b1, W2);

    dim3 pg((N + 127) / 128, 3);
    precompute_mma_kernel<<<pg, 256, SM_PRE_TOTAL>>>(x, W1, W2, b2, batch, N);

    edge_mma_kernel<<<(E + 127) / 128, 256, SM_EDGE_TOTAL>>>(edge_attr, W1, ei, E);

    node_kernel<<<(N + 127) / 128, 256>>>(W2, out, N);
}